// round 5
// baseline (speedup 1.0000x reference)
#include <cuda_runtime.h>
#include <cuda_bf16.h>
#include <math_constants.h>

// Problem constants
#define BB 4
#define TT 2048
#define BT 8192          // B*T
#define DIM 1024
#define HH 16
#define DD 64            // DIM_INNER
#define DOUT 1024
#define CHUNK 128
#define NCH (TT / CHUNK) // 16
#define NBH (BB * HH)    // 64

// ---------------- scratch (device globals; no allocations allowed) -------
__device__ float g_qk[DIM * HH];            // folded q @ Wk  : [i][h]
__device__ float g_Wv[DIM * DIM];           // packed V weight: [i][h*64+o]
__device__ float g_v[(size_t)BT * DIM];     // v activations  : [bt][h*64+o]
__device__ float g_st[BT * HH];             // scores         : [bt][h]
__device__ float g_agg[NBH * NCH * 66];     // chunk aggregates (m,u,w[64])
__device__ float g_pref[NBH * NCH * 66];    // exclusive chunk prefixes
__device__ float g_hdiv[(size_t)BT * DIM];  // per-head w/u   : [bt][h*64+d]
__device__ float g_hmean[BT * DD];          // head-mean      : [bt][d]

// ---------------- weight packing ----------------------------------------
__global__ void pack_wv(const float* __restrict__ kvk) {
    int idx = blockIdx.x * 256 + threadIdx.x;      // over 1024*1024
    if (idx < DIM * DIM) g_Wv[idx] = kvk[(size_t)idx * 2 + 1];
}

__global__ void pack_qk(const float* __restrict__ kvk, const float* __restrict__ q) {
    int idx = blockIdx.x * 256 + threadIdx.x;      // over 1024*16
    if (idx >= DIM * HH) return;
    int i = idx >> 4, h = idx & 15;
    const float* kp = kvk + (size_t)i * 2048 + h * 128;  // (h*64+o)*2, k=0
    const float* qp = q + h * DD;
    float s = 0.f;
#pragma unroll
    for (int o = 0; o < DD; o++) s += qp[o] * kp[o * 2];
    g_qk[i * HH + h] = s;                          // layout [i][h]
}

// ---------------- main GEMM: v = x @ Wv   (8192x1024x1024 fp32) ---------
__global__ __launch_bounds__(256, 2) void gemm_v(const float* __restrict__ x) {
    __shared__ float As[16][132];  // [k][m], padded
    __shared__ float Bs[16][128];  // [k][n]
    int tid = threadIdx.x;
    int tx = tid & 15, ty = tid >> 4;
    int m0 = blockIdx.y * 128, n0 = blockIdx.x * 128;

    float acc[8][8];
#pragma unroll
    for (int i = 0; i < 8; i++)
#pragma unroll
        for (int j = 0; j < 8; j++) acc[i][j] = 0.f;

    const float* Ap = x + (size_t)m0 * DIM;
    const float* Bp = g_Wv + n0;

    for (int k0 = 0; k0 < DIM; k0 += 16) {
#pragma unroll
        for (int i = 0; i < 2; i++) {              // A tile 128x16
            int idx = tid + i * 256;
            int row = idx >> 2, kq = idx & 3;
            float4 a = *(const float4*)(Ap + (size_t)row * DIM + k0 + kq * 4);
            As[kq * 4 + 0][row] = a.x; As[kq * 4 + 1][row] = a.y;
            As[kq * 4 + 2][row] = a.z; As[kq * 4 + 3][row] = a.w;
        }
#pragma unroll
        for (int i = 0; i < 2; i++) {              // B tile 16x128
            int idx = tid + i * 256;
            int kr = idx >> 5, nq = idx & 31;
            *(float4*)(&Bs[kr][nq * 4]) =
                *(const float4*)(Bp + (size_t)(k0 + kr) * DIM + nq * 4);
        }
        __syncthreads();
#pragma unroll
        for (int k = 0; k < 16; k++) {
            float a[8], b[8];
#pragma unroll
            for (int i = 0; i < 8; i++) a[i] = As[k][ty * 8 + i];
#pragma unroll
            for (int j = 0; j < 8; j++) b[j] = Bs[k][tx * 8 + j];
#pragma unroll
            for (int i = 0; i < 8; i++)
#pragma unroll
                for (int j = 0; j < 8; j++) acc[i][j] += a[i] * b[j];
        }
        __syncthreads();
    }
    float* Cp = g_v + (size_t)m0 * DIM + n0;
#pragma unroll
    for (int i = 0; i < 8; i++) {
        int row = ty * 8 + i;
#pragma unroll
        for (int j = 0; j < 8; j += 4) {
            float4 v4 = make_float4(acc[i][j], acc[i][j + 1], acc[i][j + 2], acc[i][j + 3]);
            *(float4*)(Cp + (size_t)row * DIM + tx * 8 + j) = v4;
        }
    }
}

// ---------------- st = x @ qk  (8192x16x1024) ----------------------------
__global__ void gemm_st(const float* __restrict__ x) {
    __shared__ float Xs[8][128];
    __shared__ float Qs[128][16];
    int r0 = blockIdx.x * 8;
    int tid = threadIdx.x;                         // 128 threads
    int rr = tid >> 4, hh = tid & 15;
    float acc = 0.f;
    for (int k0 = 0; k0 < DIM; k0 += 128) {
#pragma unroll
        for (int i = tid; i < 256; i += 128) {     // 8x128 floats
            int rw = i >> 5, kq = i & 31;
            ((float4*)Xs[rw])[kq] = ((const float4*)(x + (size_t)(r0 + rw) * DIM + k0))[kq];
        }
#pragma unroll
        for (int i = tid; i < 512; i += 128)       // 128x16 floats
            ((float4*)&Qs[0][0])[i] = ((const float4*)(g_qk + (size_t)k0 * HH))[i];
        __syncthreads();
#pragma unroll 8
        for (int k = 0; k < 128; k++) acc += Xs[rr][k] * Qs[k][hh];
        __syncthreads();
    }
    g_st[(size_t)(r0 + rr) * HH + hh] = acc;
}

// ---------------- scan pass 1: per-chunk aggregates ----------------------
__global__ void scan_pass1() {
    int blk = blockIdx.x;                 // bh*16 + c
    int c = blk & 15, bh = blk >> 4;
    int b = bh >> 4, h = bh & 15;
    int row0 = b * TT + c * CHUNK;
    __shared__ float sst[CHUNK];
    int d = threadIdx.x;                  // 64 threads
    for (int i = d; i < CHUNK; i += 64) sst[i] = g_st[(size_t)(row0 + i) * HH + h];
    __syncthreads();
    float m = -CUDART_INF_F, u = 0.f, w = 0.f;
    const float* vp = g_v + (size_t)row0 * DIM + h * DD + d;
    for (int t = 0; t < CHUNK; t++) {
        float s = sst[t];
        float vt = vp[(size_t)t * DIM];
        float nm = fmaxf(m, s);
        float ea = __expf(m - nm);
        float eb = __expf(s - nm);
        u = u * ea + eb;
        w = w * ea + vt * eb;
        m = nm;
    }
    float* ag = g_agg + (size_t)blk * 66;
    if (d == 0) { ag[0] = m; ag[1] = u; }
    ag[2 + d] = w;
}

// ---------------- scan pass 2: exclusive prefix over chunks --------------
__global__ void scan_pass2() {
    int bh = blockIdx.x;                  // 64 blocks
    int d = threadIdx.x;                  // 64 threads
    float Pm = -CUDART_INF_F, Pu = 0.f, Pw = 0.f;
    for (int c = 0; c < NCH; c++) {
        float* pr = g_pref + ((size_t)bh * NCH + c) * 66;
        if (d == 0) { pr[0] = Pm; pr[1] = Pu; }
        pr[2 + d] = Pw;
        const float* ag = g_agg + ((size_t)bh * NCH + c) * 66;
        float Am = ag[0], Au = ag[1], Aw = ag[2 + d];
        float nm = fmaxf(Pm, Am);
        float ea = __expf(Pm - nm), eb = __expf(Am - nm);
        Pu = Pu * ea + Au * eb;
        Pw = Pw * ea + Aw * eb;
        Pm = nm;
    }
}

// ---------------- scan pass 3: rescan with prefix, emit w/u --------------
__global__ void scan_pass3() {
    int blk = blockIdx.x;
    int c = blk & 15, bh = blk >> 4;
    int b = bh >> 4, h = bh & 15;
    int row0 = b * TT + c * CHUNK;
    __shared__ float sst[CHUNK];
    int d = threadIdx.x;
    for (int i = d; i < CHUNK; i += 64) sst[i] = g_st[(size_t)(row0 + i) * HH + h];
    __syncthreads();
    const float* pr = g_pref + ((size_t)bh * NCH + c) * 66;
    float m = pr[0], u = pr[1], w = pr[2 + d];
    const float* vp = g_v + (size_t)row0 * DIM + h * DD + d;
    float* hp = g_hdiv + (size_t)row0 * DIM + h * DD + d;
    for (int t = 0; t < CHUNK; t++) {
        float s = sst[t];
        float vt = vp[(size_t)t * DIM];
        float nm = fmaxf(m, s);
        float ea = __expf(m - nm), eb = __expf(s - nm);
        u = u * ea + eb;
        w = w * ea + vt * eb;
        m = nm;
        hp[(size_t)t * DIM] = __fdividef(w, u);
    }
}

// ---------------- head mean ----------------------------------------------
__global__ void reduce_heads() {
    int idx = blockIdx.x * 256 + threadIdx.x;   // over 8192*64
    if (idx >= BT * DD) return;
    int bt = idx >> 6, d = idx & 63;
    const float* p = g_hdiv + (size_t)bt * DIM + d;
    float s = 0.f;
#pragma unroll
    for (int h = 0; h < HH; h++) s += p[h * DD];
    g_hmean[idx] = s * (1.0f / HH);
}

// ---------------- output GEMM: out = hmean @ out_w^T + b -----------------
__global__ void gemm_out(const float* __restrict__ out_w,
                         const float* __restrict__ out_b,
                         float* __restrict__ out) {
    __shared__ float Hs[64][65];   // [r][k]
    __shared__ float Ws[64][68];   // [k][o]
    int m0 = blockIdx.y * 64, n0 = blockIdx.x * 64;
    int tid = threadIdx.x;         // 256
    const float* hsrc = g_hmean + (size_t)m0 * DD;
    for (int i = tid; i < 64 * 64; i += 256) Hs[i >> 6][i & 63] = hsrc[i];
    for (int i = tid; i < 64 * 64; i += 256) {
        int o = i >> 6, d = i & 63;
        Ws[d][o] = out_w[(size_t)(n0 + o) * DD + d];
    }
    __syncthreads();
    int tr = tid >> 4, tc = tid & 15;   // 16x16 threads, 4x4 micro-tile
    float acc[4][4];
#pragma unroll
    for (int i = 0; i < 4; i++)
#pragma unroll
        for (int j = 0; j < 4; j++) acc[i][j] = 0.f;
#pragma unroll 8
    for (int k = 0; k < 64; k++) {
        float a[4], bv[4];
#pragma unroll
        for (int i = 0; i < 4; i++) a[i] = Hs[tr * 4 + i][k];
#pragma unroll
        for (int j = 0; j < 4; j++) bv[j] = Ws[k][tc * 4 + j];
#pragma unroll
        for (int i = 0; i < 4; i++)
#pragma unroll
            for (int j = 0; j < 4; j++) acc[i][j] += a[i] * bv[j];
    }
    float bo[4];
#pragma unroll
    for (int j = 0; j < 4; j++) bo[j] = out_b[n0 + tc * 4 + j];
#pragma unroll
    for (int i = 0; i < 4; i++) {
        float4 v4 = make_float4(acc[i][0] + bo[0], acc[i][1] + bo[1],
                                acc[i][2] + bo[2], acc[i][3] + bo[3]);
        *(float4*)(out + (size_t)(m0 + tr * 4 + i) * DOUT + n0 + tc * 4) = v4;
    }
}

// ---------------- launch -------------------------------------------------
extern "C" void kernel_launch(void* const* d_in, const int* in_sizes, int n_in,
                              void* d_out, int out_size) {
    const float* x    = (const float*)d_in[0];   // [4,2048,1024]
    const float* kvk  = (const float*)d_in[1];   // [1024,16,64,2]
    const float* q    = (const float*)d_in[2];   // [16,64]
    const float* outw = (const float*)d_in[3];   // [1024,64]
    const float* outb = (const float*)d_in[4];   // [1024]
    float* out = (float*)d_out;                  // [4,2048,1024]

    pack_wv<<<(DIM * DIM + 255) / 256, 256>>>(kvk);
    pack_qk<<<(DIM * HH + 255) / 256, 256>>>(kvk, q);
    gemm_v<<<dim3(DIM / 128, BT / 128), 256>>>(x);
    gemm_st<<<BT / 8, 128>>>(x);
    scan_pass1<<<NBH * NCH, 64>>>();
    scan_pass2<<<NBH, 64>>>();
    scan_pass3<<<NBH * NCH, 64>>>();
    reduce_heads<<<(BT * DD + 255) / 256, 256>>>();
    gemm_out<<<dim3(DOUT / 64, BT / 64), 256>>>(outw, outb, out);
}

// round 7
// speedup vs baseline: 1.7621x; 1.7621x over previous
#include <cuda_runtime.h>
#include <cuda_bf16.h>
#include <math_constants.h>
#include <cstdint>

// Problem constants
#define BB 4
#define TT 2048
#define BT 8192          // B*T
#define DIM 1024
#define HH 16
#define DD 64            // DIM_INNER
#define DOUT 1024
#define CHUNK 128
#define NCH (TT / CHUNK) // 16
#define NBH (BB * HH)    // 64

// ===================== PTX helpers (non-'a' safe: sm_80+) =================
__device__ __forceinline__ uint32_t smem_u32(const void* p) {
    uint32_t a;
    asm("{ .reg .u64 t; cvta.to.shared.u64 t, %1; cvt.u32.u64 %0, t; }" : "=r"(a) : "l"(p));
    return a;
}
#define CP_ASYNC16(dst, src) \
    asm volatile("cp.async.cg.shared.global [%0], [%1], 16;" :: "r"(dst), "l"(src))
#define CP_COMMIT() asm volatile("cp.async.commit_group;" ::: "memory")
#define CP_WAIT1() asm volatile("cp.async.wait_group 1;" ::: "memory")
#define CP_WAIT0() asm volatile("cp.async.wait_group 0;" ::: "memory")
#define SW128(off) ((off) ^ (((off) >> 3) & 0x70))

#define LDMATRIX_X4(r0, r1, r2, r3, addr)                                     \
    asm volatile("ldmatrix.sync.aligned.m8n8.x4.shared.b16 {%0,%1,%2,%3}, [%4];" \
                 : "=r"(r0), "=r"(r1), "=r"(r2), "=r"(r3) : "r"(addr))

#define MMA_BF16(c0, c1, c2, c3, a0, a1, a2, a3, b0, b1)                      \
    asm volatile("mma.sync.aligned.m16n8k16.row.col.f32.bf16.bf16.f32 "       \
                 "{%0,%1,%2,%3}, {%4,%5,%6,%7}, {%8,%9}, {%0,%1,%2,%3};"      \
                 : "+f"(c0), "+f"(c1), "+f"(c2), "+f"(c3)                     \
                 : "r"(a0), "r"(a1), "r"(a2), "r"(a3), "r"(b0), "r"(b1))

// ---------------- scratch (device globals; no allocations allowed) -------
__device__ float g_qk[DIM * HH];                      // folded q @ Wk : [i][h]
__device__ __nv_bfloat16 g_xh[(size_t)BT * DIM];      // x hi (bf16)
__device__ __nv_bfloat16 g_xl[(size_t)BT * DIM];      // x lo (bf16)
__device__ __nv_bfloat16 g_wh[(size_t)DIM * DIM];     // Wv^T hi : [n][k]
__device__ __nv_bfloat16 g_wl[(size_t)DIM * DIM];     // Wv^T lo : [n][k]
__device__ float g_v[(size_t)BT * DIM];               // v activations
__device__ float g_st[BT * HH];                       // scores
__device__ float g_agg[NBH * NCH * 66];
__device__ float g_pref[NBH * NCH * 66];
__device__ float g_hdiv[(size_t)BT * DIM];
__device__ float g_hmean[BT * DD];

// ---------------- packing ------------------------------------------------
__global__ void pack_x(const float* __restrict__ x) {
    int idx = blockIdx.x * 256 + threadIdx.x;       // float4 index over BT*DIM/4
    float4 a = ((const float4*)x)[idx];
    __nv_bfloat16 h0 = __float2bfloat16_rn(a.x), h1 = __float2bfloat16_rn(a.y);
    __nv_bfloat16 h2 = __float2bfloat16_rn(a.z), h3 = __float2bfloat16_rn(a.w);
    __nv_bfloat162* ph = (__nv_bfloat162*)g_xh;
    __nv_bfloat162* pl = (__nv_bfloat162*)g_xl;
    ph[idx * 2 + 0] = __nv_bfloat162(h0, h1);
    ph[idx * 2 + 1] = __nv_bfloat162(h2, h3);
    __nv_bfloat16 l0 = __float2bfloat16_rn(a.x - __bfloat162float(h0));
    __nv_bfloat16 l1 = __float2bfloat16_rn(a.y - __bfloat162float(h1));
    __nv_bfloat16 l2 = __float2bfloat16_rn(a.z - __bfloat162float(h2));
    __nv_bfloat16 l3 = __float2bfloat16_rn(a.w - __bfloat162float(h3));
    pl[idx * 2 + 0] = __nv_bfloat162(l0, l1);
    pl[idx * 2 + 1] = __nv_bfloat162(l2, l3);
}

// transpose+split Wv: g_wh[n][i] = hi(kvk[i][n(=h*64+o)][1])
__global__ void pack_w(const float* __restrict__ kvk) {
    __shared__ float tile[32][33];
    int bi = blockIdx.x * 32;   // k (i) base
    int bn = blockIdx.y * 32;   // n base
    int tx = threadIdx.x & 31, ty = threadIdx.x >> 5;   // 32x8
#pragma unroll
    for (int k = 0; k < 4; k++) {
        int il = ty + k * 8;
        tile[il][tx] = kvk[(size_t)(bi + il) * 2048 + (bn + tx) * 2 + 1];
    }
    __syncthreads();
#pragma unroll
    for (int k = 0; k < 4; k++) {
        int nl = ty + k * 8;
        float a = tile[tx][nl];
        __nv_bfloat16 h = __float2bfloat16_rn(a);
        __nv_bfloat16 l = __float2bfloat16_rn(a - __bfloat162float(h));
        g_wh[(size_t)(bn + nl) * DIM + bi + tx] = h;
        g_wl[(size_t)(bn + nl) * DIM + bi + tx] = l;
    }
}

__global__ void pack_qk(const float* __restrict__ kvk, const float* __restrict__ q) {
    int idx = blockIdx.x * 256 + threadIdx.x;      // over 1024*16
    if (idx >= DIM * HH) return;
    int i = idx >> 4, h = idx & 15;
    const float* kp = kvk + (size_t)i * 2048 + h * 128;  // (h*64+o)*2, k=0
    const float* qp = q + h * DD;
    float s = 0.f;
#pragma unroll
    for (int o = 0; o < DD; o++) s += qp[o] * kp[o * 2];
    g_qk[i * HH + h] = s;
}

// ============== main GEMM: v = x @ Wv via mma.sync split-bf16 =============
// D = Ah@Bh^T + Ah@Bl^T + Al@Bh^T, fp32 accumulation in registers.
// CTA tile 128x128, K-chunk 64 (128B rows, SW128), 48 chunks.
// 8 warps in 2(M) x 4(N) grid, warp tile 64x32.
#define GV_TM 128
#define GV_TN 128
#define GV_KC 64
#define GV_NCHUNK 48
#define GV_A_BYTES (GV_TM * 128)                 // 16 KB
#define GV_B_BYTES (GV_TN * 128)                 // 16 KB
#define GV_STAGE_BYTES (GV_A_BYTES + GV_B_BYTES) // 32 KB
#define GV_SMEM_TOTAL (2 * GV_STAGE_BYTES)       // 64 KB

__global__ __launch_bounds__(256, 2) void gemm_v_tc() {
    extern __shared__ char smem[];
    uint32_t sbase = smem_u32(smem);
    int tid = threadIdx.x;
    int wid = tid >> 5, lane = tid & 31;
    int n0 = blockIdx.x * GV_TN;
    int m0 = blockIdx.y * GV_TM;
    int wm = wid >> 2;          // 0..1  -> rows [wm*64, wm*64+64)
    int wn = wid & 3;           // 0..3  -> cols [wn*32, wn*32+32)

    float acc[4][4][4];         // [mi][ni][4]
#pragma unroll
    for (int mi = 0; mi < 4; mi++)
#pragma unroll
        for (int ni = 0; ni < 4; ni++)
#pragma unroll
            for (int j = 0; j < 4; j++) acc[mi][ni][j] = 0.f;

    // ---- chunk loader: 2048 x 16B cp.async per chunk, 8 per thread ----
    auto load_chunk = [&](int c, uint32_t stage_off) {
        int p = c >> 4;
        int kc = (c & 15) << 6;           // k offset in elements
        const __nv_bfloat16* gA = (p < 2) ? g_xh : g_xl;
        const __nv_bfloat16* gB = (p == 1) ? g_wl : g_wh;
#pragma unroll
        for (int i = 0; i < 8; i++) {
            int seg = tid + (i << 8);
            if (seg < 1024) {             // A: 128 rows x 8 16B-chunks
                int r = seg >> 3, jb = seg & 7;
                uint32_t off = (uint32_t)((r << 7) + (jb << 4));
                uint32_t dst = sbase + stage_off + SW128(off);
                const void* src = gA + (size_t)(m0 + r) * DIM + kc + (jb << 3);
                CP_ASYNC16(dst, src);
            } else {                      // B: 128 rows x 8 16B-chunks
                int s2 = seg - 1024;
                int n = s2 >> 3, jb = s2 & 7;
                uint32_t off = (uint32_t)((n << 7) + (jb << 4));
                uint32_t dst = sbase + stage_off + GV_A_BYTES + SW128(off);
                const void* src = gB + (size_t)(n0 + n) * DIM + kc + (jb << 3);
                CP_ASYNC16(dst, src);
            }
        }
        CP_COMMIT();
    };

    const uint32_t stage_off[2] = {0u, (uint32_t)GV_STAGE_BYTES};

    // precomputed ldmatrix lane addressing (byte offsets within tile, pre-swizzle)
    // A: lane -> row (lane&15), k-16B-chunk select (lane>>4)
    int a_row = lane & 15, a_cs = lane >> 4;
    // B: lanes 0-7:(n0-7,klo) 8-15:(n0-7,khi) 16-23:(n8-15,klo) 24-31:(n8-15,khi)
    int b_row = ((lane >> 4) << 3) + (lane & 7), b_cs = (lane >> 3) & 1;

    load_chunk(0, stage_off[0]);

    for (int c = 0; c < GV_NCHUNK; c++) {
        int s = c & 1;
        if (c + 1 < GV_NCHUNK) { load_chunk(c + 1, stage_off[1 - s]); CP_WAIT1(); }
        else CP_WAIT0();
        __syncthreads();

        uint32_t abase = sbase + stage_off[s];
        uint32_t bbase = sbase + stage_off[s] + GV_A_BYTES;
#pragma unroll
        for (int ks = 0; ks < 4; ks++) {
            uint32_t afr[4][4];
#pragma unroll
            for (int mi = 0; mi < 4; mi++) {
                int row = wm * 64 + mi * 16 + a_row;
                uint32_t off = (uint32_t)((row << 7) + ((ks * 2 + a_cs) << 4));
                LDMATRIX_X4(afr[mi][0], afr[mi][1], afr[mi][2], afr[mi][3],
                            abase + SW128(off));
            }
            uint32_t bfr[4][2];
#pragma unroll
            for (int nib = 0; nib < 2; nib++) {
                int row = wn * 32 + nib * 16 + b_row;
                uint32_t off = (uint32_t)((row << 7) + ((ks * 2 + b_cs) << 4));
                uint32_t r0, r1, r2, r3;
                LDMATRIX_X4(r0, r1, r2, r3, bbase + SW128(off));
                bfr[nib * 2 + 0][0] = r0; bfr[nib * 2 + 0][1] = r1;
                bfr[nib * 2 + 1][0] = r2; bfr[nib * 2 + 1][1] = r3;
            }
#pragma unroll
            for (int mi = 0; mi < 4; mi++)
#pragma unroll
                for (int ni = 0; ni < 4; ni++)
                    MMA_BF16(acc[mi][ni][0], acc[mi][ni][1], acc[mi][ni][2], acc[mi][ni][3],
                             afr[mi][0], afr[mi][1], afr[mi][2], afr[mi][3],
                             bfr[ni][0], bfr[ni][1]);
        }
        __syncthreads();
    }

    // ---- epilogue: c-frag m16n8 layout -> g_v ----
    int gid = lane >> 2, tig = lane & 3;
#pragma unroll
    for (int mi = 0; mi < 4; mi++) {
        int r0 = m0 + wm * 64 + mi * 16 + gid;
#pragma unroll
        for (int ni = 0; ni < 4; ni++) {
            int col = n0 + wn * 32 + ni * 8 + tig * 2;
            *(float2*)(g_v + (size_t)r0 * DIM + col) =
                make_float2(acc[mi][ni][0], acc[mi][ni][1]);
            *(float2*)(g_v + (size_t)(r0 + 8) * DIM + col) =
                make_float2(acc[mi][ni][2], acc[mi][ni][3]);
        }
    }
}

// ---------------- st = x @ qk  (8192x16x1024) ----------------------------
__global__ void gemm_st(const float* __restrict__ x) {
    __shared__ float Xs[8][128];
    __shared__ float Qs[128][16];
    int r0 = blockIdx.x * 8;
    int tid = threadIdx.x;                         // 128 threads
    int rr = tid >> 4, hh = tid & 15;
    float acc = 0.f;
    for (int k0 = 0; k0 < DIM; k0 += 128) {
#pragma unroll
        for (int i = tid; i < 256; i += 128) {
            int rw = i >> 5, kq = i & 31;
            ((float4*)Xs[rw])[kq] = ((const float4*)(x + (size_t)(r0 + rw) * DIM + k0))[kq];
        }
#pragma unroll
        for (int i = tid; i < 512; i += 128)
            ((float4*)&Qs[0][0])[i] = ((const float4*)(g_qk + (size_t)k0 * HH))[i];
        __syncthreads();
#pragma unroll 8
        for (int k = 0; k < 128; k++) acc += Xs[rr][k] * Qs[k][hh];
        __syncthreads();
    }
    g_st[(size_t)(r0 + rr) * HH + hh] = acc;
}

// ---------------- scan pass 1: per-chunk aggregates ----------------------
__global__ void scan_pass1() {
    int blk = blockIdx.x;
    int c = blk & 15, bh = blk >> 4;
    int b = bh >> 4, h = bh & 15;
    int row0 = b * TT + c * CHUNK;
    __shared__ float sst[CHUNK];
    int d = threadIdx.x;                  // 64 threads
    for (int i = d; i < CHUNK; i += 64) sst[i] = g_st[(size_t)(row0 + i) * HH + h];
    __syncthreads();
    float m = -CUDART_INF_F, u = 0.f, w = 0.f;
    const float* vp = g_v + (size_t)row0 * DIM + h * DD + d;
    for (int t = 0; t < CHUNK; t++) {
        float s = sst[t];
        float vt = vp[(size_t)t * DIM];
        float nm = fmaxf(m, s);
        float ea = __expf(m - nm);
        float eb = __expf(s - nm);
        u = u * ea + eb;
        w = w * ea + vt * eb;
        m = nm;
    }
    float* ag = g_agg + (size_t)blk * 66;
    if (d == 0) { ag[0] = m; ag[1] = u; }
    ag[2 + d] = w;
}

// ---------------- scan pass 2: exclusive prefix over chunks --------------
__global__ void scan_pass2() {
    int bh = blockIdx.x;
    int d = threadIdx.x;
    float Pm = -CUDART_INF_F, Pu = 0.f, Pw = 0.f;
    for (int c = 0; c < NCH; c++) {
        float* pr = g_pref + ((size_t)bh * NCH + c) * 66;
        if (d == 0) { pr[0] = Pm; pr[1] = Pu; }
        pr[2 + d] = Pw;
        const float* ag = g_agg + ((size_t)bh * NCH + c) * 66;
        float Am = ag[0], Au = ag[1], Aw = ag[2 + d];
        float nm = fmaxf(Pm, Am);
        float ea = __expf(Pm - nm), eb = __expf(Am - nm);
        Pu = Pu * ea + Au * eb;
        Pw = Pw * ea + Aw * eb;
        Pm = nm;
    }
}

// ---------------- scan pass 3: rescan with prefix, emit w/u --------------
__global__ void scan_pass3() {
    int blk = blockIdx.x;
    int c = blk & 15, bh = blk >> 4;
    int b = bh >> 4, h = bh & 15;
    int row0 = b * TT + c * CHUNK;
    __shared__ float sst[CHUNK];
    int d = threadIdx.x;
    for (int i = d; i < CHUNK; i += 64) sst[i] = g_st[(size_t)(row0 + i) * HH + h];
    __syncthreads();
    const float* pr = g_pref + ((size_t)bh * NCH + c) * 66;
    float m = pr[0], u = pr[1], w = pr[2 + d];
    const float* vp = g_v + (size_t)row0 * DIM + h * DD + d;
    float* hp = g_hdiv + (size_t)row0 * DIM + h * DD + d;
    for (int t = 0; t < CHUNK; t++) {
        float s = sst[t];
        float vt = vp[(size_t)t * DIM];
        float nm = fmaxf(m, s);
        float ea = __expf(m - nm), eb = __expf(s - nm);
        u = u * ea + eb;
        w = w * ea + vt * eb;
        m = nm;
        hp[(size_t)t * DIM] = __fdividef(w, u);
    }
}

// ---------------- head mean ----------------------------------------------
__global__ void reduce_heads() {
    int idx = blockIdx.x * 256 + threadIdx.x;
    if (idx >= BT * DD) return;
    int bt = idx >> 6, d = idx & 63;
    const float* p = g_hdiv + (size_t)bt * DIM + d;
    float s = 0.f;
#pragma unroll
    for (int h = 0; h < HH; h++) s += p[h * DD];
    g_hmean[idx] = s * (1.0f / HH);
}

// ---------------- output GEMM: out = hmean @ out_w^T + b -----------------
__global__ void gemm_out(const float* __restrict__ out_w,
                         const float* __restrict__ out_b,
                         float* __restrict__ out) {
    __shared__ float Hs[64][65];
    __shared__ float Ws[64][68];
    int m0 = blockIdx.y * 64, n0 = blockIdx.x * 64;
    int tid = threadIdx.x;
    const float* hsrc = g_hmean + (size_t)m0 * DD;
    for (int i = tid; i < 64 * 64; i += 256) Hs[i >> 6][i & 63] = hsrc[i];
    for (int i = tid; i < 64 * 64; i += 256) {
        int o = i >> 6, d = i & 63;
        Ws[d][o] = out_w[(size_t)(n0 + o) * DD + d];
    }
    __syncthreads();
    int tr = tid >> 4, tc = tid & 15;
    float acc[4][4];
#pragma unroll
    for (int i = 0; i < 4; i++)
#pragma unroll
        for (int j = 0; j < 4; j++) acc[i][j] = 0.f;
#pragma unroll 8
    for (int k = 0; k < 64; k++) {
        float a[4], bv[4];
#pragma unroll
        for (int i = 0; i < 4; i++) a[i] = Hs[tr * 4 + i][k];
#pragma unroll
        for (int j = 0; j < 4; j++) bv[j] = Ws[k][tc * 4 + j];
#pragma unroll
        for (int i = 0; i < 4; i++)
#pragma unroll
            for (int j = 0; j < 4; j++) acc[i][j] += a[i] * bv[j];
    }
    float bo[4];
#pragma unroll
    for (int j = 0; j < 4; j++) bo[j] = out_b[n0 + tc * 4 + j];
#pragma unroll
    for (int i = 0; i < 4; i++) {
        float4 v4 = make_float4(acc[i][0] + bo[0], acc[i][1] + bo[1],
                                acc[i][2] + bo[2], acc[i][3] + bo[3]);
        *(float4*)(out + (size_t)(m0 + tr * 4 + i) * DOUT + n0 + tc * 4) = v4;
    }
}

// ---------------- launch -------------------------------------------------
extern "C" void kernel_launch(void* const* d_in, const int* in_sizes, int n_in,
                              void* d_out, int out_size) {
    const float* x    = (const float*)d_in[0];   // [4,2048,1024]
    const float* kvk  = (const float*)d_in[1];   // [1024,16,64,2]
    const float* q    = (const float*)d_in[2];   // [16,64]
    const float* outw = (const float*)d_in[3];   // [1024,64]
    const float* outb = (const float*)d_in[4];   // [1024]
    float* out = (float*)d_out;                  // [4,2048,1024]

    cudaFuncSetAttribute(gemm_v_tc, cudaFuncAttributeMaxDynamicSharedMemorySize,
                         GV_SMEM_TOTAL);

    pack_x<<<(BT * DIM / 4) / 256, 256>>>(x);
    pack_w<<<dim3(DIM / 32, DIM / 32), 256>>>(kvk);
    pack_qk<<<(DIM * HH + 255) / 256, 256>>>(kvk, q);
    gemm_v_tc<<<dim3(DIM / GV_TN, BT / GV_TM), 256, GV_SMEM_TOTAL>>>();
    gemm_st<<<BT / 8, 128>>>(x);
    scan_pass1<<<NBH * NCH, 64>>>();
    scan_pass2<<<NBH, 64>>>();
    scan_pass3<<<NBH * NCH, 64>>>();
    reduce_heads<<<(BT * DD + 255) / 256, 256>>>();
    gemm_out<<<dim3(DOUT / 64, BT / 64), 256>>>(outw, outb, out);
}

// round 8
// speedup vs baseline: 1.9059x; 1.0816x over previous
#include <cuda_runtime.h>
#include <cuda_bf16.h>
#include <math_constants.h>
#include <cstdint>

// Problem constants
#define BB 4
#define TT 2048
#define BT 8192          // B*T
#define DIM 1024
#define HH 16
#define DD 64            // DIM_INNER
#define DOUT 1024
#define CHUNK 128
#define NCH (TT / CHUNK) // 16
#define NBH (BB * HH)    // 64

// ===================== PTX helpers (non-'a' safe: sm_80+) =================
__device__ __forceinline__ uint32_t smem_u32(const void* p) {
    uint32_t a;
    asm("{ .reg .u64 t; cvta.to.shared.u64 t, %1; cvt.u32.u64 %0, t; }" : "=r"(a) : "l"(p));
    return a;
}
#define CP_ASYNC16(dst, src) \
    asm volatile("cp.async.cg.shared.global [%0], [%1], 16;" :: "r"(dst), "l"(src))
#define CP_COMMIT() asm volatile("cp.async.commit_group;" ::: "memory")
#define CP_WAIT0() asm volatile("cp.async.wait_group 0;" ::: "memory")
#define SW128(off) ((off) ^ (((off) >> 3) & 0x70))

#define LDMATRIX_X4(r0, r1, r2, r3, addr)                                     \
    asm volatile("ldmatrix.sync.aligned.m8n8.x4.shared.b16 {%0,%1,%2,%3}, [%4];" \
                 : "=r"(r0), "=r"(r1), "=r"(r2), "=r"(r3) : "r"(addr))

#define MMA_BF16(c0, c1, c2, c3, a0, a1, a2, a3, b0, b1)                      \
    asm volatile("mma.sync.aligned.m16n8k16.row.col.f32.bf16.bf16.f32 "       \
                 "{%0,%1,%2,%3}, {%4,%5,%6,%7}, {%8,%9}, {%0,%1,%2,%3};"      \
                 : "+f"(c0), "+f"(c1), "+f"(c2), "+f"(c3)                     \
                 : "r"(a0), "r"(a1), "r"(a2), "r"(a3), "r"(b0), "r"(b1))

// ---------------- scratch (device globals; no allocations allowed) -------
__device__ float g_qk[DIM * HH];                      // folded q @ Wk : [i][h]
__device__ __nv_bfloat16 g_xh[(size_t)BT * DIM];      // x hi (bf16)
__device__ __nv_bfloat16 g_xl[(size_t)BT * DIM];      // x lo (bf16)
__device__ __nv_bfloat16 g_wh[(size_t)DIM * DIM];     // Wv^T hi : [n][k]
__device__ __nv_bfloat16 g_wl[(size_t)DIM * DIM];     // Wv^T lo : [n][k]
__device__ float g_v[(size_t)BT * DIM];               // v activations
__device__ float g_st[BT * HH];                       // scores
__device__ float g_agg[NBH * NCH * 66];
__device__ float g_pref[NBH * NCH * 66];
__device__ float g_hdiv[(size_t)BT * DIM];
__device__ float g_hmean[BT * DD];

// ---------------- packing ------------------------------------------------
__global__ void pack_x(const float* __restrict__ x) {
    int idx = blockIdx.x * 256 + threadIdx.x;       // float4 index over BT*DIM/4
    float4 a = ((const float4*)x)[idx];
    __nv_bfloat16 h0 = __float2bfloat16_rn(a.x), h1 = __float2bfloat16_rn(a.y);
    __nv_bfloat16 h2 = __float2bfloat16_rn(a.z), h3 = __float2bfloat16_rn(a.w);
    __nv_bfloat162* ph = (__nv_bfloat162*)g_xh;
    __nv_bfloat162* pl = (__nv_bfloat162*)g_xl;
    ph[idx * 2 + 0] = __nv_bfloat162(h0, h1);
    ph[idx * 2 + 1] = __nv_bfloat162(h2, h3);
    __nv_bfloat16 l0 = __float2bfloat16_rn(a.x - __bfloat162float(h0));
    __nv_bfloat16 l1 = __float2bfloat16_rn(a.y - __bfloat162float(h1));
    __nv_bfloat16 l2 = __float2bfloat16_rn(a.z - __bfloat162float(h2));
    __nv_bfloat16 l3 = __float2bfloat16_rn(a.w - __bfloat162float(h3));
    pl[idx * 2 + 0] = __nv_bfloat162(l0, l1);
    pl[idx * 2 + 1] = __nv_bfloat162(l2, l3);
}

// transpose+split Wv: g_wh[n][i] = hi(kvk[i][n(=h*64+o)][1])
__global__ void pack_w(const float* __restrict__ kvk) {
    __shared__ float tile[32][33];
    int bi = blockIdx.x * 32;   // k (i) base
    int bn = blockIdx.y * 32;   // n base
    int tx = threadIdx.x & 31, ty = threadIdx.x >> 5;   // 32x8
#pragma unroll
    for (int k = 0; k < 4; k++) {
        int il = ty + k * 8;
        tile[il][tx] = kvk[(size_t)(bi + il) * 2048 + (bn + tx) * 2 + 1];
    }
    __syncthreads();
#pragma unroll
    for (int k = 0; k < 4; k++) {
        int nl = ty + k * 8;
        float a = tile[tx][nl];
        __nv_bfloat16 h = __float2bfloat16_rn(a);
        __nv_bfloat16 l = __float2bfloat16_rn(a - __bfloat162float(h));
        g_wh[(size_t)(bn + nl) * DIM + bi + tx] = h;
        g_wl[(size_t)(bn + nl) * DIM + bi + tx] = l;
    }
}

__global__ void pack_qk(const float* __restrict__ kvk, const float* __restrict__ q) {
    int idx = blockIdx.x * 256 + threadIdx.x;      // over 1024*16
    if (idx >= DIM * HH) return;
    int i = idx >> 4, h = idx & 15;
    const float* kp = kvk + (size_t)i * 2048 + h * 128;  // (h*64+o)*2, k=0
    const float* qp = q + h * DD;
    float s = 0.f;
#pragma unroll
    for (int o = 0; o < DD; o++) s += qp[o] * kp[o * 2];
    g_qk[i * HH + h] = s;
}

// ============== main GEMM: v = x @ Wv via mma.sync split-bf16 =============
// D = Ah@Bh^T + Ah@Bl^T + Al@Bh^T, fp32 accumulation in registers.
// CTA tile 128x128, 4 warps in 2(M)x2(N), warp tile 64x64.
// K-chunk 64 (128B rows, SW128), 48 chunks, single-sync 2-stage pipeline.
#define GV_TM 128
#define GV_TN 128
#define GV_NCHUNK 48
#define GV_A_BYTES (GV_TM * 128)                 // 16 KB
#define GV_B_BYTES (GV_TN * 128)                 // 16 KB
#define GV_STAGE_BYTES (GV_A_BYTES + GV_B_BYTES) // 32 KB
#define GV_SMEM_TOTAL (2 * GV_STAGE_BYTES)       // 64 KB

__global__ __launch_bounds__(128, 2) void gemm_v_tc() {
    extern __shared__ char smem[];
    uint32_t sbase = smem_u32(smem);
    int tid = threadIdx.x;
    int wid = tid >> 5, lane = tid & 31;
    int n0 = blockIdx.x * GV_TN;
    int m0 = blockIdx.y * GV_TM;
    int wm = wid >> 1;          // 0..1 -> rows [wm*64, wm*64+64)
    int wn = wid & 1;           // 0..1 -> cols [wn*64, wn*64+64)

    float acc[4][8][4];         // [mi 16-rows][ni 8-cols][frag]
#pragma unroll
    for (int mi = 0; mi < 4; mi++)
#pragma unroll
        for (int ni = 0; ni < 8; ni++)
#pragma unroll
            for (int j = 0; j < 4; j++) acc[mi][ni][j] = 0.f;

    // ---- chunk loader: 2048 x 16B cp.async per chunk, 16 per thread ----
    auto load_chunk = [&](int c, uint32_t stage_off) {
        int p = c >> 4;
        int kc = (c & 15) << 6;           // k offset in elements
        const __nv_bfloat16* gA = (p < 2) ? g_xh : g_xl;
        const __nv_bfloat16* gB = (p == 1) ? g_wl : g_wh;
#pragma unroll
        for (int i = 0; i < 16; i++) {
            int seg = tid + (i << 7);
            if (seg < 1024) {             // A: 128 rows x 8 16B-chunks
                int r = seg >> 3, jb = seg & 7;
                uint32_t off = (uint32_t)((r << 7) + (jb << 4));
                uint32_t dst = sbase + stage_off + SW128(off);
                const void* src = gA + (size_t)(m0 + r) * DIM + kc + (jb << 3);
                CP_ASYNC16(dst, src);
            } else {                      // B: 128 rows x 8 16B-chunks
                int s2 = seg - 1024;
                int n = s2 >> 3, jb = s2 & 7;
                uint32_t off = (uint32_t)((n << 7) + (jb << 4));
                uint32_t dst = sbase + stage_off + GV_A_BYTES + SW128(off);
                const void* src = gB + (size_t)(n0 + n) * DIM + kc + (jb << 3);
                CP_ASYNC16(dst, src);
            }
        }
        CP_COMMIT();
    };

    const uint32_t stage_off[2] = {0u, (uint32_t)GV_STAGE_BYTES};

    // ldmatrix lane addressing (validated in R6):
    // A x4: lanes 0-15 rows m0-15 @ k-lo16B, lanes 16-31 rows m0-15 @ k-hi16B
    int a_row = lane & 15, a_cs = lane >> 4;
    // B x4: frag regs (n0-7,klo),(n0-7,khi),(n8-15,klo),(n8-15,khi)
    int b_row = ((lane >> 4) << 3) + (lane & 7), b_cs = (lane >> 3) & 1;

    load_chunk(0, stage_off[0]);

    for (int c = 0; c < GV_NCHUNK; c++) {
        int s = c & 1;
        CP_WAIT0();                       // chunk c resident
        __syncthreads();                  // all warps done reading buffer s
        if (c + 1 < GV_NCHUNK) load_chunk(c + 1, stage_off[1 - s]);

        uint32_t abase = sbase + stage_off[s];
        uint32_t bbase = sbase + stage_off[s] + GV_A_BYTES;
#pragma unroll
        for (int ks = 0; ks < 4; ks++) {
            uint32_t afr[4][4];
#pragma unroll
            for (int mi = 0; mi < 4; mi++) {
                int row = wm * 64 + mi * 16 + a_row;
                uint32_t off = (uint32_t)((row << 7) + ((ks * 2 + a_cs) << 4));
                LDMATRIX_X4(afr[mi][0], afr[mi][1], afr[mi][2], afr[mi][3],
                            abase + SW128(off));
            }
            uint32_t bfr[8][2];
#pragma unroll
            for (int nj = 0; nj < 4; nj++) {
                int row = wn * 64 + nj * 16 + b_row;
                uint32_t off = (uint32_t)((row << 7) + ((ks * 2 + b_cs) << 4));
                uint32_t r0, r1, r2, r3;
                LDMATRIX_X4(r0, r1, r2, r3, bbase + SW128(off));
                bfr[nj * 2 + 0][0] = r0; bfr[nj * 2 + 0][1] = r1;
                bfr[nj * 2 + 1][0] = r2; bfr[nj * 2 + 1][1] = r3;
            }
#pragma unroll
            for (int mi = 0; mi < 4; mi++)
#pragma unroll
                for (int ni = 0; ni < 8; ni++)
                    MMA_BF16(acc[mi][ni][0], acc[mi][ni][1], acc[mi][ni][2], acc[mi][ni][3],
                             afr[mi][0], afr[mi][1], afr[mi][2], afr[mi][3],
                             bfr[ni][0], bfr[ni][1]);
        }
    }

    // ---- epilogue: c-frag m16n8 layout -> g_v ----
    int gid = lane >> 2, tig = lane & 3;
#pragma unroll
    for (int mi = 0; mi < 4; mi++) {
        int r0 = m0 + wm * 64 + mi * 16 + gid;
#pragma unroll
        for (int ni = 0; ni < 8; ni++) {
            int col = n0 + wn * 64 + ni * 8 + tig * 2;
            *(float2*)(g_v + (size_t)r0 * DIM + col) =
                make_float2(acc[mi][ni][0], acc[mi][ni][1]);
            *(float2*)(g_v + (size_t)(r0 + 8) * DIM + col) =
                make_float2(acc[mi][ni][2], acc[mi][ni][3]);
        }
    }
}

// ---------------- st = x @ qk  (8192x16x1024), float4-per-thread ----------
__global__ __launch_bounds__(128) void gemm_st(const float* __restrict__ x) {
    __shared__ float Xs[32][128];
    __shared__ float Qs[128 * 16];
    int r0 = blockIdx.x * 32;
    int tid = threadIdx.x;                         // 128 threads
    int rr = tid >> 2, hg = tid & 3;               // 32 rows x 4 head-groups
    float4 acc = make_float4(0.f, 0.f, 0.f, 0.f);
    for (int k0 = 0; k0 < DIM; k0 += 128) {
#pragma unroll
        for (int i = 0; i < 8; i++) {              // 32x128 floats, 8 f4/thread
            int idx = tid + i * 128;
            int rw = idx >> 5, kq = idx & 31;
            ((float4*)Xs[rw])[kq] = ((const float4*)(x + (size_t)(r0 + rw) * DIM + k0))[kq];
        }
#pragma unroll
        for (int i = 0; i < 4; i++)                // 128x16 floats, 4 f4/thread
            ((float4*)Qs)[tid + i * 128] = ((const float4*)(g_qk + (size_t)k0 * HH))[tid + i * 128];
        __syncthreads();
#pragma unroll 8
        for (int k = 0; k < 128; k++) {
            float a = Xs[rr][k];
            float4 q = ((const float4*)Qs)[k * 4 + hg];
            acc.x += a * q.x; acc.y += a * q.y;
            acc.z += a * q.z; acc.w += a * q.w;
        }
        __syncthreads();
    }
    ((float4*)g_st)[(size_t)(r0 + rr) * 4 + hg] = acc;
}

// ---------------- scan pass 1: per-chunk aggregates ----------------------
__global__ void scan_pass1() {
    int blk = blockIdx.x;
    int c = blk & 15, bh = blk >> 4;
    int b = bh >> 4, h = bh & 15;
    int row0 = b * TT + c * CHUNK;
    __shared__ float sst[CHUNK];
    int d = threadIdx.x;                  // 64 threads
    for (int i = d; i < CHUNK; i += 64) sst[i] = g_st[(size_t)(row0 + i) * HH + h];
    __syncthreads();
    float m = -CUDART_INF_F, u = 0.f, w = 0.f;
    const float* vp = g_v + (size_t)row0 * DIM + h * DD + d;
    for (int t = 0; t < CHUNK; t++) {
        float s = sst[t];
        float vt = vp[(size_t)t * DIM];
        float nm = fmaxf(m, s);
        float ea = __expf(m - nm);
        float eb = __expf(s - nm);
        u = u * ea + eb;
        w = w * ea + vt * eb;
        m = nm;
    }
    float* ag = g_agg + (size_t)blk * 66;
    if (d == 0) { ag[0] = m; ag[1] = u; }
    ag[2 + d] = w;
}

// ---------------- scan pass 2: exclusive prefix over chunks --------------
__global__ void scan_pass2() {
    int bh = blockIdx.x;
    int d = threadIdx.x;
    float Pm = -CUDART_INF_F, Pu = 0.f, Pw = 0.f;
    for (int c = 0; c < NCH; c++) {
        float* pr = g_pref + ((size_t)bh * NCH + c) * 66;
        if (d == 0) { pr[0] = Pm; pr[1] = Pu; }
        pr[2 + d] = Pw;
        const float* ag = g_agg + ((size_t)bh * NCH + c) * 66;
        float Am = ag[0], Au = ag[1], Aw = ag[2 + d];
        float nm = fmaxf(Pm, Am);
        float ea = __expf(Pm - nm), eb = __expf(Am - nm);
        Pu = Pu * ea + Au * eb;
        Pw = Pw * ea + Aw * eb;
        Pm = nm;
    }
}

// ---------------- scan pass 3: rescan with prefix, emit w/u --------------
__global__ void scan_pass3() {
    int blk = blockIdx.x;
    int c = blk & 15, bh = blk >> 4;
    int b = bh >> 4, h = bh & 15;
    int row0 = b * TT + c * CHUNK;
    __shared__ float sst[CHUNK];
    int d = threadIdx.x;
    for (int i = d; i < CHUNK; i += 64) sst[i] = g_st[(size_t)(row0 + i) * HH + h];
    __syncthreads();
    const float* pr = g_pref + ((size_t)bh * NCH + c) * 66;
    float m = pr[0], u = pr[1], w = pr[2 + d];
    const float* vp = g_v + (size_t)row0 * DIM + h * DD + d;
    float* hp = g_hdiv + (size_t)row0 * DIM + h * DD + d;
    for (int t = 0; t < CHUNK; t++) {
        float s = sst[t];
        float vt = vp[(size_t)t * DIM];
        float nm = fmaxf(m, s);
        float ea = __expf(m - nm), eb = __expf(s - nm);
        u = u * ea + eb;
        w = w * ea + vt * eb;
        m = nm;
        hp[(size_t)t * DIM] = __fdividef(w, u);
    }
}

// ---------------- head mean ----------------------------------------------
__global__ void reduce_heads() {
    int idx = blockIdx.x * 256 + threadIdx.x;
    if (idx >= BT * DD) return;
    int bt = idx >> 6, d = idx & 63;
    const float* p = g_hdiv + (size_t)bt * DIM + d;
    float s = 0.f;
#pragma unroll
    for (int h = 0; h < HH; h++) s += p[h * DD];
    g_hmean[idx] = s * (1.0f / HH);
}

// ---------------- output GEMM: out = hmean @ out_w^T + b -----------------
__global__ void gemm_out(const float* __restrict__ out_w,
                         const float* __restrict__ out_b,
                         float* __restrict__ out) {
    __shared__ float Hs[64][65];
    __shared__ float Ws[64][68];
    int m0 = blockIdx.y * 64, n0 = blockIdx.x * 64;
    int tid = threadIdx.x;
    const float* hsrc = g_hmean + (size_t)m0 * DD;
    for (int i = tid; i < 64 * 64; i += 256) Hs[i >> 6][i & 63] = hsrc[i];
    for (int i = tid; i < 64 * 64; i += 256) {
        int o = i >> 6, d = i & 63;
        Ws[d][o] = out_w[(size_t)(n0 + o) * DD + d];
    }
    __syncthreads();
    int tr = tid >> 4, tc = tid & 15;
    float acc[4][4];
#pragma unroll
    for (int i = 0; i < 4; i++)
#pragma unroll
        for (int j = 0; j < 4; j++) acc[i][j] = 0.f;
#pragma unroll 8
    for (int k = 0; k < 64; k++) {
        float a[4], bv[4];
#pragma unroll
        for (int i = 0; i < 4; i++) a[i] = Hs[tr * 4 + i][k];
#pragma unroll
        for (int j = 0; j < 4; j++) bv[j] = Ws[k][tc * 4 + j];
#pragma unroll
        for (int i = 0; i < 4; i++)
#pragma unroll
            for (int j = 0; j < 4; j++) acc[i][j] += a[i] * bv[j];
    }
    float bo[4];
#pragma unroll
    for (int j = 0; j < 4; j++) bo[j] = out_b[n0 + tc * 4 + j];
#pragma unroll
    for (int i = 0; i < 4; i++) {
        float4 v4 = make_float4(acc[i][0] + bo[0], acc[i][1] + bo[1],
                                acc[i][2] + bo[2], acc[i][3] + bo[3]);
        *(float4*)(out + (size_t)(m0 + tr * 4 + i) * DOUT + n0 + tc * 4) = v4;
    }
}

// ---------------- launch -------------------------------------------------
extern "C" void kernel_launch(void* const* d_in, const int* in_sizes, int n_in,
                              void* d_out, int out_size) {
    const float* x    = (const float*)d_in[0];   // [4,2048,1024]
    const float* kvk  = (const float*)d_in[1];   // [1024,16,64,2]
    const float* q    = (const float*)d_in[2];   // [16,64]
    const float* outw = (const float*)d_in[3];   // [1024,64]
    const float* outb = (const float*)d_in[4];   // [1024]
    float* out = (float*)d_out;                  // [4,2048,1024]

    cudaFuncSetAttribute(gemm_v_tc, cudaFuncAttributeMaxDynamicSharedMemorySize,
                         GV_SMEM_TOTAL);

    pack_x<<<(BT * DIM / 4) / 256, 256>>>(x);
    pack_w<<<dim3(DIM / 32, DIM / 32), 256>>>(kvk);
    pack_qk<<<(DIM * HH + 255) / 256, 256>>>(kvk, q);
    gemm_v_tc<<<dim3(DIM / GV_TN, BT / GV_TM), 128, GV_SMEM_TOTAL>>>();
    gemm_st<<<BT / 32, 128>>>(x);
    scan_pass1<<<NBH * NCH, 64>>>();
    scan_pass2<<<NBH, 64>>>();
    scan_pass3<<<NBH * NCH, 64>>>();
    reduce_heads<<<(BT * DD + 255) / 256, 256>>>();
    gemm_out<<<dim3(DOUT / 64, BT / 64), 256>>>(outw, outb, out);
}

// round 11
// speedup vs baseline: 2.0010x; 1.0499x over previous
#include <cuda_runtime.h>
#include <cuda_bf16.h>
#include <math_constants.h>
#include <cstdint>

// Problem constants
#define BB 4
#define TT 2048
#define BT 8192          // B*T
#define DIM 1024
#define HH 16
#define DD 64            // DIM_INNER
#define DOUT 1024
#define WCH 64           // w-pipeline chunk rows
#define NWC (TT / WCH)   // 32
#define NBH (BB * HH)    // 64

// ===================== PTX helpers (non-'a' safe: sm_80+) =================
__device__ __forceinline__ uint32_t smem_u32(const void* p) {
    uint32_t a;
    asm("{ .reg .u64 t; cvta.to.shared.u64 t, %1; cvt.u32.u64 %0, t; }" : "=r"(a) : "l"(p));
    return a;
}
#define CP_ASYNC16(dst, src) \
    asm volatile("cp.async.cg.shared.global [%0], [%1], 16;" :: "r"(dst), "l"(src))
#define CP_COMMIT() asm volatile("cp.async.commit_group;" ::: "memory")
#define CP_WAIT1() asm volatile("cp.async.wait_group 1;" ::: "memory")
#define CP_WAIT0() asm volatile("cp.async.wait_group 0;" ::: "memory")
#define SW128(off) ((off) ^ (((off) >> 3) & 0x70))

#define LDMATRIX_X4(r0, r1, r2, r3, addr)                                     \
    asm volatile("ldmatrix.sync.aligned.m8n8.x4.shared.b16 {%0,%1,%2,%3}, [%4];" \
                 : "=r"(r0), "=r"(r1), "=r"(r2), "=r"(r3) : "r"(addr))

#define MMA_BF16(c0, c1, c2, c3, a0, a1, a2, a3, b0, b1)                      \
    asm volatile("mma.sync.aligned.m16n8k16.row.col.f32.bf16.bf16.f32 "       \
                 "{%0,%1,%2,%3}, {%4,%5,%6,%7}, {%8,%9}, {%0,%1,%2,%3};"      \
                 : "+f"(c0), "+f"(c1), "+f"(c2), "+f"(c3)                     \
                 : "r"(a0), "r"(a1), "r"(a2), "r"(a3), "r"(b0), "r"(b1))

// ---------------- scratch (device globals; no allocations allowed) -------
__device__ float g_qk[DIM * HH];                      // folded q @ Wk : [i][h]
__device__ __nv_bfloat16 g_xh[(size_t)BT * DIM];      // x hi (bf16)
__device__ __nv_bfloat16 g_xl[(size_t)BT * DIM];      // x lo (bf16)
__device__ __nv_bfloat16 g_wh[(size_t)DIM * DIM];     // Wv^T hi : [n][k]
__device__ __nv_bfloat16 g_wl[(size_t)DIM * DIM];     // Wv^T lo : [n][k]
__device__ float g_v[(size_t)BT * DIM];               // v activations
__device__ float g_st[BT * HH];                       // scores [bt][h]
__device__ float g_stT[NBH * TT];                     // scores [bh][t]
__device__ float g_gq[NBH * TT];                      // g_t = exp(st - m*)
__device__ float g_rq[NBH * TT];                      // r_t = 1 / cumsum(g)
__device__ float g_ws[BB * NWC * DIM];                // chunk sums of v*g
__device__ float g_wpre[BB * NWC * DIM];              // exclusive chunk prefix
__device__ float g_hmean[BT * DD];                    // head-mean

// ---------------- packing ------------------------------------------------
__global__ void pack_x(const float* __restrict__ x) {
    int idx = blockIdx.x * 256 + threadIdx.x;       // float4 index over BT*DIM/4
    float4 a = ((const float4*)x)[idx];
    __nv_bfloat16 h0 = __float2bfloat16_rn(a.x), h1 = __float2bfloat16_rn(a.y);
    __nv_bfloat16 h2 = __float2bfloat16_rn(a.z), h3 = __float2bfloat16_rn(a.w);
    __nv_bfloat162* ph = (__nv_bfloat162*)g_xh;
    __nv_bfloat162* pl = (__nv_bfloat162*)g_xl;
    ph[idx * 2 + 0] = __nv_bfloat162(h0, h1);
    ph[idx * 2 + 1] = __nv_bfloat162(h2, h3);
    __nv_bfloat16 l0 = __float2bfloat16_rn(a.x - __bfloat162float(h0));
    __nv_bfloat16 l1 = __float2bfloat16_rn(a.y - __bfloat162float(h1));
    __nv_bfloat16 l2 = __float2bfloat16_rn(a.z - __bfloat162float(h2));
    __nv_bfloat16 l3 = __float2bfloat16_rn(a.w - __bfloat162float(h3));
    pl[idx * 2 + 0] = __nv_bfloat162(l0, l1);
    pl[idx * 2 + 1] = __nv_bfloat162(l2, l3);
}

// transpose+split Wv: g_wh[n][i] = hi(kvk[i][n(=h*64+o)][1])
__global__ void pack_w(const float* __restrict__ kvk) {
    __shared__ float tile[32][33];
    int bi = blockIdx.x * 32;   // k (i) base
    int bn = blockIdx.y * 32;   // n base
    int tx = threadIdx.x & 31, ty = threadIdx.x >> 5;   // 32x8
#pragma unroll
    for (int k = 0; k < 4; k++) {
        int il = ty + k * 8;
        tile[il][tx] = kvk[(size_t)(bi + il) * 2048 + (bn + tx) * 2 + 1];
    }
    __syncthreads();
#pragma unroll
    for (int k = 0; k < 4; k++) {
        int nl = ty + k * 8;
        float a = tile[tx][nl];
        __nv_bfloat16 h = __float2bfloat16_rn(a);
        __nv_bfloat16 l = __float2bfloat16_rn(a - __bfloat162float(h));
        g_wh[(size_t)(bn + nl) * DIM + bi + tx] = h;
        g_wl[(size_t)(bn + nl) * DIM + bi + tx] = l;
    }
}

__global__ void pack_qk(const float* __restrict__ kvk, const float* __restrict__ q) {
    int idx = blockIdx.x * 256 + threadIdx.x;      // over 1024*16
    if (idx >= DIM * HH) return;
    int i = idx >> 4, h = idx & 15;
    const float* kp = kvk + (size_t)i * 2048 + h * 128;  // (h*64+o)*2, k=0
    const float* qp = q + h * DD;
    float s = 0.f;
#pragma unroll
    for (int o = 0; o < DD; o++) s += qp[o] * kp[o * 2];
    g_qk[i * HH + h] = s;
}

// ============== main GEMM: v = x @ Wv via mma.sync split-bf16 =============
// D = Ah@Bh^T + Ah@Bl^T + Al@Bh^T, fp32 accumulation in registers.
// CTA tile 128x128, 4 warps 2x2, warp tile 64x64. 3-stage cp.async pipeline.
#define GV_TM 128
#define GV_TN 128
#define GV_NCHUNK 48
#define GV_A_BYTES (GV_TM * 128)                 // 16 KB
#define GV_B_BYTES (GV_TN * 128)                 // 16 KB
#define GV_STAGE_BYTES (GV_A_BYTES + GV_B_BYTES) // 32 KB
#define GV_SMEM_TOTAL (3 * GV_STAGE_BYTES)       // 96 KB

__global__ __launch_bounds__(128, 2) void gemm_v_tc() {
    extern __shared__ char smem[];
    uint32_t sbase = smem_u32(smem);
    int tid = threadIdx.x;
    int wid = tid >> 5, lane = tid & 31;
    int n0 = blockIdx.x * GV_TN;
    int m0 = blockIdx.y * GV_TM;
    int wm = wid >> 1;
    int wn = wid & 1;

    float acc[4][8][4];
#pragma unroll
    for (int mi = 0; mi < 4; mi++)
#pragma unroll
        for (int ni = 0; ni < 8; ni++)
#pragma unroll
            for (int j = 0; j < 4; j++) acc[mi][ni][j] = 0.f;

    auto load_chunk = [&](int c, uint32_t stage_off) {
        int p = c >> 4;
        int kc = (c & 15) << 6;
        const __nv_bfloat16* gA = (p < 2) ? g_xh : g_xl;
        const __nv_bfloat16* gB = (p == 1) ? g_wl : g_wh;
#pragma unroll
        for (int i = 0; i < 16; i++) {
            int seg = tid + (i << 7);
            if (seg < 1024) {
                int r = seg >> 3, jb = seg & 7;
                uint32_t off = (uint32_t)((r << 7) + (jb << 4));
                uint32_t dst = sbase + stage_off + SW128(off);
                const void* src = gA + (size_t)(m0 + r) * DIM + kc + (jb << 3);
                CP_ASYNC16(dst, src);
            } else {
                int s2 = seg - 1024;
                int n = s2 >> 3, jb = s2 & 7;
                uint32_t off = (uint32_t)((n << 7) + (jb << 4));
                uint32_t dst = sbase + stage_off + GV_A_BYTES + SW128(off);
                const void* src = gB + (size_t)(n0 + n) * DIM + kc + (jb << 3);
                CP_ASYNC16(dst, src);
            }
        }
        CP_COMMIT();
    };

    const uint32_t stage_off[3] = {0u, (uint32_t)GV_STAGE_BYTES, (uint32_t)(2 * GV_STAGE_BYTES)};

    int a_row = lane & 15, a_cs = lane >> 4;
    int b_row = ((lane >> 4) << 3) + (lane & 7), b_cs = (lane >> 3) & 1;

    load_chunk(0, stage_off[0]);
    load_chunk(1, stage_off[1]);

    for (int c = 0; c < GV_NCHUNK; c++) {
        int s = c % 3;
        if (c < GV_NCHUNK - 1) CP_WAIT1(); else CP_WAIT0();
        __syncthreads();                   // all warps done reading stage (c-1)%3
        if (c + 2 < GV_NCHUNK) load_chunk(c + 2, stage_off[(c + 2) % 3]);

        uint32_t abase = sbase + stage_off[s];
        uint32_t bbase = sbase + stage_off[s] + GV_A_BYTES;
#pragma unroll
        for (int ks = 0; ks < 4; ks++) {
            uint32_t afr[4][4];
#pragma unroll
            for (int mi = 0; mi < 4; mi++) {
                int row = wm * 64 + mi * 16 + a_row;
                uint32_t off = (uint32_t)((row << 7) + ((ks * 2 + a_cs) << 4));
                LDMATRIX_X4(afr[mi][0], afr[mi][1], afr[mi][2], afr[mi][3],
                            abase + SW128(off));
            }
            uint32_t bfr[8][2];
#pragma unroll
            for (int nj = 0; nj < 4; nj++) {
                int row = wn * 64 + nj * 16 + b_row;
                uint32_t off = (uint32_t)((row << 7) + ((ks * 2 + b_cs) << 4));
                uint32_t r0, r1, r2, r3;
                LDMATRIX_X4(r0, r1, r2, r3, bbase + SW128(off));
                bfr[nj * 2 + 0][0] = r0; bfr[nj * 2 + 0][1] = r1;
                bfr[nj * 2 + 1][0] = r2; bfr[nj * 2 + 1][1] = r3;
            }
#pragma unroll
            for (int mi = 0; mi < 4; mi++)
#pragma unroll
                for (int ni = 0; ni < 8; ni++)
                    MMA_BF16(acc[mi][ni][0], acc[mi][ni][1], acc[mi][ni][2], acc[mi][ni][3],
                             afr[mi][0], afr[mi][1], afr[mi][2], afr[mi][3],
                             bfr[ni][0], bfr[ni][1]);
        }
    }

    int gid = lane >> 2, tig = lane & 3;
#pragma unroll
    for (int mi = 0; mi < 4; mi++) {
        int r0 = m0 + wm * 64 + mi * 16 + gid;
#pragma unroll
        for (int ni = 0; ni < 8; ni++) {
            int col = n0 + wn * 64 + ni * 8 + tig * 2;
            *(float2*)(g_v + (size_t)r0 * DIM + col) =
                make_float2(acc[mi][ni][0], acc[mi][ni][1]);
            *(float2*)(g_v + (size_t)(r0 + 8) * DIM + col) =
                make_float2(acc[mi][ni][2], acc[mi][ni][3]);
        }
    }
}

// ---------------- st = x @ qk  (8192x16x1024), writes both layouts -------
__global__ __launch_bounds__(128) void gemm_st(const float* __restrict__ x) {
    __shared__ float Xs[32][128];
    __shared__ float Qs[128 * 16];
    int r0 = blockIdx.x * 32;
    int tid = threadIdx.x;
    int rr = tid >> 2, hg = tid & 3;
    float4 acc = make_float4(0.f, 0.f, 0.f, 0.f);
    for (int k0 = 0; k0 < DIM; k0 += 128) {
#pragma unroll
        for (int i = 0; i < 8; i++) {
            int idx = tid + i * 128;
            int rw = idx >> 5, kq = idx & 31;
            ((float4*)Xs[rw])[kq] = ((const float4*)(x + (size_t)(r0 + rw) * DIM + k0))[kq];
        }
#pragma unroll
        for (int i = 0; i < 4; i++)
            ((float4*)Qs)[tid + i * 128] = ((const float4*)(g_qk + (size_t)k0 * HH))[tid + i * 128];
        __syncthreads();
#pragma unroll 8
        for (int k = 0; k < 128; k++) {
            float a = Xs[rr][k];
            float4 q = ((const float4*)Qs)[k * 4 + hg];
            acc.x += a * q.x; acc.y += a * q.y;
            acc.z += a * q.z; acc.w += a * q.w;
        }
        __syncthreads();
    }
    int bt = r0 + rr;
    ((float4*)g_st)[(size_t)bt * 4 + hg] = acc;
    int b = bt >> 11, t = bt & 2047;
    int bh = b * HH + hg * 4;
    g_stT[(size_t)(bh + 0) * TT + t] = acc.x;
    g_stT[(size_t)(bh + 1) * TT + t] = acc.y;
    g_stT[(size_t)(bh + 2) * TT + t] = acc.z;
    g_stT[(size_t)(bh + 3) * TT + t] = acc.w;
}

// ------------- k_g: per-(bh) max, g_t = exp(st-m*), r_t = 1/cumsum(g) ----
// Exclusive prefix taken as sc[tid-1] (additions-only) — NOT inclusive-minus-
// own-run, which catastrophically cancels when own run >> prefix.
__global__ __launch_bounds__(128) void k_g() {
    int bh = blockIdx.x;                 // 64
    int tid = threadIdx.x;               // 128, each owns 16 consecutive t
    const float* stp = g_stT + (size_t)bh * TT;
    float s[16];
#pragma unroll
    for (int j = 0; j < 16; j++) s[j] = stp[tid * 16 + j];
    float lm = s[0];
#pragma unroll
    for (int j = 1; j < 16; j++) lm = fmaxf(lm, s[j]);
    __shared__ float sc[128];
    sc[tid] = lm;
    __syncthreads();
#pragma unroll
    for (int off = 64; off > 0; off >>= 1) {
        if (tid < off) sc[tid] = fmaxf(sc[tid], sc[tid + off]);
        __syncthreads();
    }
    float mstar = sc[0];
    __syncthreads();
    float g[16];
    float run = 0.f;
#pragma unroll
    for (int j = 0; j < 16; j++) { g[j] = __expf(s[j] - mstar); run += g[j]; }
    // block inclusive scan of thread totals (Hillis-Steele)
    sc[tid] = run;
    __syncthreads();
#pragma unroll
    for (int off = 1; off < 128; off <<= 1) {
        float v = (tid >= off) ? sc[tid - off] : 0.f;
        __syncthreads();
        sc[tid] += v;
        __syncthreads();
    }
    float cum = (tid == 0) ? 0.f : sc[tid - 1];   // exclusive, additions-only
    float* gg = g_gq + (size_t)bh * TT + tid * 16;
    float* gr = g_rq + (size_t)bh * TT + tid * 16;
#pragma unroll
    for (int j = 0; j < 16; j++) {
        cum += g[j];
        gg[j] = g[j];
        gr[j] = __fdividef(1.f, fmaxf(cum, 1e-37f));
    }
}

// ------------- k_w1: chunk sums of v*g over 64-row chunks ----------------
__global__ __launch_bounds__(512) void k_w1() {
    int c = blockIdx.x;                  // 32
    int hq = blockIdx.y;                 // 2
    int b = blockIdx.z;                  // 4
    int tid = threadIdx.x;               // 512: hh(8) x d(64)
    int hh = tid >> 6, d = tid & 63;
    __shared__ float gs[8][64];
    gs[hh][d] = g_gq[(size_t)(b * HH + hq * 8 + hh) * TT + c * WCH + d];
    __syncthreads();
    int row0 = b * TT + c * WCH;
    const float* vp = g_v + (size_t)row0 * DIM + (hq * 8 + hh) * DD + d;
    float w = 0.f;
#pragma unroll 8
    for (int t = 0; t < WCH; t++) w += vp[(size_t)t * DIM] * gs[hh][t];
    g_ws[((b * NWC + c) << 10) + (hq * 8 + hh) * DD + d] = w;
}

// ------------- k_w2: exclusive prefix over chunks ------------------------
__global__ __launch_bounds__(1024) void k_w2() {
    int b = blockIdx.x;                  // 4
    int tid = threadIdx.x;               // 1024 = h*64+d
    float v[NWC];
#pragma unroll
    for (int c = 0; c < NWC; c++) v[c] = g_ws[((b * NWC + c) << 10) + tid];
    float p = 0.f;
#pragma unroll
    for (int c = 0; c < NWC; c++) {
        g_wpre[((b * NWC + c) << 10) + tid] = p;
        p += v[c];
    }
}

// ------------- k_w3: cumsum + h = w*r, fused head-mean -------------------
__global__ __launch_bounds__(1024) void k_w3() {
    int c = blockIdx.x;                  // 32
    int b = blockIdx.y;                  // 4
    int tid = threadIdx.x;               // 1024 = h*64+d
    int h = tid >> 6, d = tid & 63;
    __shared__ float gs[16][64];
    __shared__ float rs[16][64];
    __shared__ float red[2][16][68];
    gs[h][d] = g_gq[(size_t)(b * HH + h) * TT + c * WCH + d];
    rs[h][d] = g_rq[(size_t)(b * HH + h) * TT + c * WCH + d];
    float w = g_wpre[((b * NWC + c) << 10) + tid];
    int row0 = b * TT + c * WCH;
    const float* vp = g_v + (size_t)row0 * DIM + tid;
    __syncthreads();
    float vnxt[4];
#pragma unroll
    for (int k = 0; k < 4; k++) vnxt[k] = vp[(size_t)k * DIM];
    for (int t = 0; t < WCH; t += 4) {
#pragma unroll
        for (int k = 0; k < 4; k++) {
            int tt = t + k;
            float vcur = vnxt[k];
            if (tt + 4 < WCH) vnxt[k] = vp[(size_t)(tt + 4) * DIM];
            w += vcur * gs[h][tt];
            red[tt & 1][h][d] = w * rs[h][tt];
            __syncthreads();
            if (tid < 64) {
                float s = 0.f;
#pragma unroll
                for (int j = 0; j < 16; j++) s += red[tt & 1][j][tid];
                g_hmean[(size_t)(row0 + tt) * DD + tid] = s * 0.0625f;
            }
        }
    }
}

// ---------------- output GEMM: out = hmean @ out_w^T + b -----------------
__global__ void gemm_out(const float* __restrict__ out_w,
                         const float* __restrict__ out_b,
                         float* __restrict__ out) {
    __shared__ float Hs[64][65];
    __shared__ float Ws[64][68];
    int m0 = blockIdx.y * 64, n0 = blockIdx.x * 64;
    int tid = threadIdx.x;
    const float* hsrc = g_hmean + (size_t)m0 * DD;
    for (int i = tid; i < 64 * 64; i += 256) Hs[i >> 6][i & 63] = hsrc[i];
    for (int i = tid; i < 64 * 64; i += 256) {
        int o = i >> 6, d = i & 63;
        Ws[d][o] = out_w[(size_t)(n0 + o) * DD + d];
    }
    __syncthreads();
    int tr = tid >> 4, tc = tid & 15;
    float acc[4][4];
#pragma unroll
    for (int i = 0; i < 4; i++)
#pragma unroll
        for (int j = 0; j < 4; j++) acc[i][j] = 0.f;
#pragma unroll 8
    for (int k = 0; k < 64; k++) {
        float a[4], bv[4];
#pragma unroll
        for (int i = 0; i < 4; i++) a[i] = Hs[tr * 4 + i][k];
#pragma unroll
        for (int j = 0; j < 4; j++) bv[j] = Ws[k][tc * 4 + j];
#pragma unroll
        for (int i = 0; i < 4; i++)
#pragma unroll
            for (int j = 0; j < 4; j++) acc[i][j] += a[i] * bv[j];
    }
    float bo[4];
#pragma unroll
    for (int j = 0; j < 4; j++) bo[j] = out_b[n0 + tc * 4 + j];
#pragma unroll
    for (int i = 0; i < 4; i++) {
        float4 v4 = make_float4(acc[i][0] + bo[0], acc[i][1] + bo[1],
                                acc[i][2] + bo[2], acc[i][3] + bo[3]);
        *(float4*)(out + (size_t)(m0 + tr * 4 + i) * DOUT + n0 + tc * 4) = v4;
    }
}

// ---------------- launch -------------------------------------------------
extern "C" void kernel_launch(void* const* d_in, const int* in_sizes, int n_in,
                              void* d_out, int out_size) {
    const float* x    = (const float*)d_in[0];   // [4,2048,1024]
    const float* kvk  = (const float*)d_in[1];   // [1024,16,64,2]
    const float* q    = (const float*)d_in[2];   // [16,64]
    const float* outw = (const float*)d_in[3];   // [1024,64]
    const float* outb = (const float*)d_in[4];   // [1024]
    float* out = (float*)d_out;                  // [4,2048,1024]

    cudaFuncSetAttribute(gemm_v_tc, cudaFuncAttributeMaxDynamicSharedMemorySize,
                         GV_SMEM_TOTAL);

    pack_x<<<(BT * DIM / 4) / 256, 256>>>(x);
    pack_w<<<dim3(DIM / 32, DIM / 32), 256>>>(kvk);
    pack_qk<<<(DIM * HH + 255) / 256, 256>>>(kvk, q);
    gemm_st<<<BT / 32, 128>>>(x);
    k_g<<<NBH, 128>>>();
    gemm_v_tc<<<dim3(DIM / GV_TN, BT / GV_TM), 128, GV_SMEM_TOTAL>>>();
    k_w1<<<dim3(NWC, 2, BB), 512>>>();
    k_w2<<<BB, 1024>>>();
    k_w3<<<dim3(NWC, BB), 1024>>>();
    gemm_out<<<dim3(DOUT / 64, BT / 64), 256>>>(outw, outb, out);
}

// round 12
// speedup vs baseline: 2.1478x; 1.0733x over previous
#include <cuda_runtime.h>
#include <cuda_bf16.h>
#include <math_constants.h>
#include <cstdint>

// Problem constants
#define BB 4
#define TT 2048
#define BT 8192          // B*T
#define DIM 1024
#define HH 16
#define DD 64            // DIM_INNER
#define DOUT 1024
#define WCH 64           // w-pipeline chunk rows
#define NWC (TT / WCH)   // 32
#define NBH (BB * HH)    // 64

// ===================== PTX helpers (non-'a' safe: sm_80+) =================
__device__ __forceinline__ uint32_t smem_u32(const void* p) {
    uint32_t a;
    asm("{ .reg .u64 t; cvta.to.shared.u64 t, %1; cvt.u32.u64 %0, t; }" : "=r"(a) : "l"(p));
    return a;
}
#define CP_ASYNC16(dst, src) \
    asm volatile("cp.async.cg.shared.global [%0], [%1], 16;" :: "r"(dst), "l"(src))
#define CP_COMMIT() asm volatile("cp.async.commit_group;" ::: "memory")
#define CP_WAIT1() asm volatile("cp.async.wait_group 1;" ::: "memory")
#define CP_WAIT0() asm volatile("cp.async.wait_group 0;" ::: "memory")
#define SW128(off) ((off) ^ (((off) >> 3) & 0x70))

#define LDMATRIX_X4(r0, r1, r2, r3, addr)                                     \
    asm volatile("ldmatrix.sync.aligned.m8n8.x4.shared.b16 {%0,%1,%2,%3}, [%4];" \
                 : "=r"(r0), "=r"(r1), "=r"(r2), "=r"(r3) : "r"(addr))

#define MMA_BF16(c0, c1, c2, c3, a0, a1, a2, a3, b0, b1)                      \
    asm volatile("mma.sync.aligned.m16n8k16.row.col.f32.bf16.bf16.f32 "       \
                 "{%0,%1,%2,%3}, {%4,%5,%6,%7}, {%8,%9}, {%0,%1,%2,%3};"      \
                 : "+f"(c0), "+f"(c1), "+f"(c2), "+f"(c3)                     \
                 : "r"(a0), "r"(a1), "r"(a2), "r"(a3), "r"(b0), "r"(b1))

// ---------------- scratch (device globals; no allocations allowed) -------
__device__ float g_qk[DIM * HH];                      // folded q @ Wk : [i][h]
__device__ __nv_bfloat16 g_xh[(size_t)BT * DIM];      // x hi (bf16)
__device__ __nv_bfloat16 g_xl[(size_t)BT * DIM];      // x lo (bf16)
__device__ __nv_bfloat16 g_wh[(size_t)DIM * DIM];     // Wv^T hi : [n][k]
__device__ __nv_bfloat16 g_wl[(size_t)DIM * DIM];     // Wv^T lo : [n][k]
__device__ __nv_bfloat16 g_qkTh[HH * DIM];            // qk^T hi : [h][k]
__device__ __nv_bfloat16 g_qkTl[HH * DIM];            // qk^T lo : [h][k]
__device__ float g_v[(size_t)BT * DIM];               // v activations
__device__ float g_stT[NBH * TT];                     // scores [bh][t]
__device__ float g_gq[NBH * TT];                      // g_t = exp(st - m*)
__device__ float g_rq[NBH * TT];                      // r_t = 1 / cumsum(g)
__device__ float g_ws[BB * NWC * DIM];                // chunk sums of v*g
__device__ float g_wpre[BB * NWC * DIM];              // exclusive chunk prefix
__device__ float g_hmean[BT * DD];                    // head-mean

// ---------------- packing ------------------------------------------------
__global__ void pack_x(const float* __restrict__ x) {
    int idx = blockIdx.x * 256 + threadIdx.x;       // float4 index over BT*DIM/4
    float4 a = ((const float4*)x)[idx];
    __nv_bfloat16 h0 = __float2bfloat16_rn(a.x), h1 = __float2bfloat16_rn(a.y);
    __nv_bfloat16 h2 = __float2bfloat16_rn(a.z), h3 = __float2bfloat16_rn(a.w);
    __nv_bfloat162* ph = (__nv_bfloat162*)g_xh;
    __nv_bfloat162* pl = (__nv_bfloat162*)g_xl;
    ph[idx * 2 + 0] = __nv_bfloat162(h0, h1);
    ph[idx * 2 + 1] = __nv_bfloat162(h2, h3);
    __nv_bfloat16 l0 = __float2bfloat16_rn(a.x - __bfloat162float(h0));
    __nv_bfloat16 l1 = __float2bfloat16_rn(a.y - __bfloat162float(h1));
    __nv_bfloat16 l2 = __float2bfloat16_rn(a.z - __bfloat162float(h2));
    __nv_bfloat16 l3 = __float2bfloat16_rn(a.w - __bfloat162float(h3));
    pl[idx * 2 + 0] = __nv_bfloat162(l0, l1);
    pl[idx * 2 + 1] = __nv_bfloat162(l2, l3);
}

// transpose+split Wv: g_wh[n][i] = hi(kvk[i][n(=h*64+o)][1])
__global__ void pack_w(const float* __restrict__ kvk) {
    __shared__ float tile[32][33];
    int bi = blockIdx.x * 32;   // k (i) base
    int bn = blockIdx.y * 32;   // n base
    int tx = threadIdx.x & 31, ty = threadIdx.x >> 5;   // 32x8
#pragma unroll
    for (int k = 0; k < 4; k++) {
        int il = ty + k * 8;
        tile[il][tx] = kvk[(size_t)(bi + il) * 2048 + (bn + tx) * 2 + 1];
    }
    __syncthreads();
#pragma unroll
    for (int k = 0; k < 4; k++) {
        int nl = ty + k * 8;
        float a = tile[tx][nl];
        __nv_bfloat16 h = __float2bfloat16_rn(a);
        __nv_bfloat16 l = __float2bfloat16_rn(a - __bfloat162float(h));
        g_wh[(size_t)(bn + nl) * DIM + bi + tx] = h;
        g_wl[(size_t)(bn + nl) * DIM + bi + tx] = l;
    }
}

__global__ void pack_qk(const float* __restrict__ kvk, const float* __restrict__ q) {
    int idx = blockIdx.x * 256 + threadIdx.x;      // over 1024*16
    if (idx >= DIM * HH) return;
    int i = idx >> 4, h = idx & 15;
    const float* kp = kvk + (size_t)i * 2048 + h * 128;  // (h*64+o)*2, k=0
    const float* qp = q + h * DD;
    float s = 0.f;
#pragma unroll
    for (int o = 0; o < DD; o++) s += qp[o] * kp[o * 2];
    g_qk[i * HH + h] = s;
}

// split+transpose qk -> [h][k] bf16 hi/lo
__global__ void pack_qkT() {
    int idx = blockIdx.x * 256 + threadIdx.x;      // over 16*1024
    int hrow = idx >> 10, k = idx & 1023;
    float a = g_qk[k * HH + hrow];
    __nv_bfloat16 h = __float2bfloat16_rn(a);
    g_qkTh[idx] = h;
    g_qkTl[idx] = __float2bfloat16_rn(a - __bfloat162float(h));
}

// ============== main GEMM: v = x @ Wv via mma.sync split-bf16 =============
// CTA tile 128x128, 4 warps 2x2, warp tile 64x64. 3-stage cp.async pipeline.
#define GV_TM 128
#define GV_TN 128
#define GV_NCHUNK 48
#define GV_A_BYTES (GV_TM * 128)                 // 16 KB
#define GV_B_BYTES (GV_TN * 128)                 // 16 KB
#define GV_STAGE_BYTES (GV_A_BYTES + GV_B_BYTES) // 32 KB
#define GV_SMEM_TOTAL (3 * GV_STAGE_BYTES)       // 96 KB

__global__ __launch_bounds__(128, 2) void gemm_v_tc() {
    extern __shared__ char smem[];
    uint32_t sbase = smem_u32(smem);
    int tid = threadIdx.x;
    int wid = tid >> 5, lane = tid & 31;
    int n0 = blockIdx.x * GV_TN;
    int m0 = blockIdx.y * GV_TM;
    int wm = wid >> 1;
    int wn = wid & 1;

    float acc[4][8][4];
#pragma unroll
    for (int mi = 0; mi < 4; mi++)
#pragma unroll
        for (int ni = 0; ni < 8; ni++)
#pragma unroll
            for (int j = 0; j < 4; j++) acc[mi][ni][j] = 0.f;

    auto load_chunk = [&](int c, uint32_t stage_off) {
        int p = c >> 4;
        int kc = (c & 15) << 6;
        const __nv_bfloat16* gA = (p < 2) ? g_xh : g_xl;
        const __nv_bfloat16* gB = (p == 1) ? g_wl : g_wh;
#pragma unroll
        for (int i = 0; i < 16; i++) {
            int seg = tid + (i << 7);
            if (seg < 1024) {
                int r = seg >> 3, jb = seg & 7;
                uint32_t off = (uint32_t)((r << 7) + (jb << 4));
                uint32_t dst = sbase + stage_off + SW128(off);
                const void* src = gA + (size_t)(m0 + r) * DIM + kc + (jb << 3);
                CP_ASYNC16(dst, src);
            } else {
                int s2 = seg - 1024;
                int n = s2 >> 3, jb = s2 & 7;
                uint32_t off = (uint32_t)((n << 7) + (jb << 4));
                uint32_t dst = sbase + stage_off + GV_A_BYTES + SW128(off);
                const void* src = gB + (size_t)(n0 + n) * DIM + kc + (jb << 3);
                CP_ASYNC16(dst, src);
            }
        }
        CP_COMMIT();
    };

    const uint32_t stage_off[3] = {0u, (uint32_t)GV_STAGE_BYTES, (uint32_t)(2 * GV_STAGE_BYTES)};

    int a_row = lane & 15, a_cs = lane >> 4;
    int b_row = ((lane >> 4) << 3) + (lane & 7), b_cs = (lane >> 3) & 1;

    load_chunk(0, stage_off[0]);
    load_chunk(1, stage_off[1]);

    for (int c = 0; c < GV_NCHUNK; c++) {
        int s = c % 3;
        if (c < GV_NCHUNK - 1) CP_WAIT1(); else CP_WAIT0();
        __syncthreads();
        if (c + 2 < GV_NCHUNK) load_chunk(c + 2, stage_off[(c + 2) % 3]);

        uint32_t abase = sbase + stage_off[s];
        uint32_t bbase = sbase + stage_off[s] + GV_A_BYTES;
#pragma unroll
        for (int ks = 0; ks < 4; ks++) {
            uint32_t afr[4][4];
#pragma unroll
            for (int mi = 0; mi < 4; mi++) {
                int row = wm * 64 + mi * 16 + a_row;
                uint32_t off = (uint32_t)((row << 7) + ((ks * 2 + a_cs) << 4));
                LDMATRIX_X4(afr[mi][0], afr[mi][1], afr[mi][2], afr[mi][3],
                            abase + SW128(off));
            }
            uint32_t bfr[8][2];
#pragma unroll
            for (int nj = 0; nj < 4; nj++) {
                int row = wn * 64 + nj * 16 + b_row;
                uint32_t off = (uint32_t)((row << 7) + ((ks * 2 + b_cs) << 4));
                uint32_t r0, r1, r2, r3;
                LDMATRIX_X4(r0, r1, r2, r3, bbase + SW128(off));
                bfr[nj * 2 + 0][0] = r0; bfr[nj * 2 + 0][1] = r1;
                bfr[nj * 2 + 1][0] = r2; bfr[nj * 2 + 1][1] = r3;
            }
#pragma unroll
            for (int mi = 0; mi < 4; mi++)
#pragma unroll
                for (int ni = 0; ni < 8; ni++)
                    MMA_BF16(acc[mi][ni][0], acc[mi][ni][1], acc[mi][ni][2], acc[mi][ni][3],
                             afr[mi][0], afr[mi][1], afr[mi][2], afr[mi][3],
                             bfr[ni][0], bfr[ni][1]);
        }
    }

    int gid = lane >> 2, tig = lane & 3;
#pragma unroll
    for (int mi = 0; mi < 4; mi++) {
        int r0 = m0 + wm * 64 + mi * 16 + gid;
#pragma unroll
        for (int ni = 0; ni < 8; ni++) {
            int col = n0 + wn * 64 + ni * 8 + tig * 2;
            *(float2*)(g_v + (size_t)r0 * DIM + col) =
                make_float2(acc[mi][ni][0], acc[mi][ni][1]);
            *(float2*)(g_v + (size_t)(r0 + 8) * DIM + col) =
                make_float2(acc[mi][ni][2], acc[mi][ni][3]);
        }
    }
}

// ============== st GEMM: st = x @ qk via mma.sync split-bf16 ==============
// M=8192, N=16, K=1024. 128 blocks x 64 rows; 4 warps, warp = 16 rows x 16 n.
#define ST_A_BYTES (64 * 128)                     // 8 KB
#define ST_B_BYTES (16 * 128)                     // 2 KB
#define ST_STAGE (ST_A_BYTES + ST_B_BYTES)        // 10 KB
#define ST_SMEM_TOTAL (3 * ST_STAGE)              // 30 KB

__global__ __launch_bounds__(128, 4) void gemm_st_tc() {
    extern __shared__ char smem[];
    uint32_t sbase = smem_u32(smem);
    int tid = threadIdx.x;
    int wid = tid >> 5, lane = tid & 31;
    int m0 = blockIdx.x * 64;

    float acc[2][4];
#pragma unroll
    for (int ni = 0; ni < 2; ni++)
#pragma unroll
        for (int j = 0; j < 4; j++) acc[ni][j] = 0.f;

    auto load_chunk = [&](int c, uint32_t stage_off) {
        int p = c >> 4;
        int kc = (c & 15) << 6;
        const __nv_bfloat16* gA = (p < 2) ? g_xh : g_xl;
        const __nv_bfloat16* gB = (p == 1) ? g_qkTl : g_qkTh;
#pragma unroll
        for (int i = 0; i < 5; i++) {
            int seg = tid + (i << 7);
            if (seg < 512) {
                int r = seg >> 3, jb = seg & 7;
                uint32_t off = (uint32_t)((r << 7) + (jb << 4));
                CP_ASYNC16(sbase + stage_off + SW128(off),
                           gA + (size_t)(m0 + r) * DIM + kc + (jb << 3));
            } else if (seg < 640) {
                int s2 = seg - 512;
                int n = s2 >> 3, jb = s2 & 7;
                uint32_t off = (uint32_t)((n << 7) + (jb << 4));
                CP_ASYNC16(sbase + stage_off + ST_A_BYTES + SW128(off),
                           gB + (size_t)n * DIM + kc + (jb << 3));
            }
        }
        CP_COMMIT();
    };

    const uint32_t stage_off[3] = {0u, (uint32_t)ST_STAGE, (uint32_t)(2 * ST_STAGE)};
    int a_row = lane & 15, a_cs = lane >> 4;
    int b_row = ((lane >> 4) << 3) + (lane & 7), b_cs = (lane >> 3) & 1;

    load_chunk(0, stage_off[0]);
    load_chunk(1, stage_off[1]);

    for (int c = 0; c < GV_NCHUNK; c++) {
        int s = c % 3;
        if (c < GV_NCHUNK - 1) CP_WAIT1(); else CP_WAIT0();
        __syncthreads();
        if (c + 2 < GV_NCHUNK) load_chunk(c + 2, stage_off[(c + 2) % 3]);

        uint32_t abase = sbase + stage_off[s];
        uint32_t bbase = sbase + stage_off[s] + ST_A_BYTES;
#pragma unroll
        for (int ks = 0; ks < 4; ks++) {
            uint32_t a0, a1, a2, a3;
            {
                int row = wid * 16 + a_row;
                uint32_t off = (uint32_t)((row << 7) + ((ks * 2 + a_cs) << 4));
                LDMATRIX_X4(a0, a1, a2, a3, abase + SW128(off));
            }
            uint32_t bfr[2][2];
            {
                uint32_t off = (uint32_t)((b_row << 7) + ((ks * 2 + b_cs) << 4));
                uint32_t r0, r1, r2, r3;
                LDMATRIX_X4(r0, r1, r2, r3, bbase + SW128(off));
                bfr[0][0] = r0; bfr[0][1] = r1;
                bfr[1][0] = r2; bfr[1][1] = r3;
            }
#pragma unroll
            for (int ni = 0; ni < 2; ni++)
                MMA_BF16(acc[ni][0], acc[ni][1], acc[ni][2], acc[ni][3],
                         a0, a1, a2, a3, bfr[ni][0], bfr[ni][1]);
        }
    }

    // epilogue: write stT[bh][t]
    int gid = lane >> 2, tig = lane & 3;
    int r = m0 + wid * 16 + gid;
    int b = r >> 11;
    int t0 = r & 2047, t8 = (r + 8) & 2047;
#pragma unroll
    for (int ni = 0; ni < 2; ni++) {
        int h0 = ni * 8 + tig * 2;
        g_stT[(size_t)(b * HH + h0) * TT + t0]     = acc[ni][0];
        g_stT[(size_t)(b * HH + h0 + 1) * TT + t0] = acc[ni][1];
        g_stT[(size_t)(b * HH + h0) * TT + t8]     = acc[ni][2];
        g_stT[(size_t)(b * HH + h0 + 1) * TT + t8] = acc[ni][3];
    }
}

// ------------- k_g: per-(bh) max, g_t = exp(st-m*), r_t = 1/cumsum(g) ----
__global__ __launch_bounds__(128) void k_g() {
    int bh = blockIdx.x;                 // 64
    int tid = threadIdx.x;               // 128, each owns 16 consecutive t
    const float* stp = g_stT + (size_t)bh * TT;
    float s[16];
#pragma unroll
    for (int j = 0; j < 16; j++) s[j] = stp[tid * 16 + j];
    float lm = s[0];
#pragma unroll
    for (int j = 1; j < 16; j++) lm = fmaxf(lm, s[j]);
    __shared__ float sc[128];
    sc[tid] = lm;
    __syncthreads();
#pragma unroll
    for (int off = 64; off > 0; off >>= 1) {
        if (tid < off) sc[tid] = fmaxf(sc[tid], sc[tid + off]);
        __syncthreads();
    }
    float mstar = sc[0];
    __syncthreads();
    float g[16];
    float run = 0.f;
#pragma unroll
    for (int j = 0; j < 16; j++) { g[j] = __expf(s[j] - mstar); run += g[j]; }
    sc[tid] = run;
    __syncthreads();
#pragma unroll
    for (int off = 1; off < 128; off <<= 1) {
        float v = (tid >= off) ? sc[tid - off] : 0.f;
        __syncthreads();
        sc[tid] += v;
        __syncthreads();
    }
    float cum = (tid == 0) ? 0.f : sc[tid - 1];   // exclusive, additions-only
    float* gg = g_gq + (size_t)bh * TT + tid * 16;
    float* gr = g_rq + (size_t)bh * TT + tid * 16;
#pragma unroll
    for (int j = 0; j < 16; j++) {
        cum += g[j];
        gg[j] = g[j];
        gr[j] = __fdividef(1.f, fmaxf(cum, 1e-37f));
    }
}

// ------------- k_w1: chunk sums of v*g over 64-row chunks ----------------
__global__ __launch_bounds__(512) void k_w1() {
    int c = blockIdx.x;                  // 32
    int hq = blockIdx.y;                 // 2
    int b = blockIdx.z;                  // 4
    int tid = threadIdx.x;               // 512: hh(8) x d(64)
    int hh = tid >> 6, d = tid & 63;
    __shared__ float gs[8][64];
    gs[hh][d] = g_gq[(size_t)(b * HH + hq * 8 + hh) * TT + c * WCH + d];
    __syncthreads();
    int row0 = b * TT + c * WCH;
    const float* vp = g_v + (size_t)row0 * DIM + (hq * 8 + hh) * DD + d;
    float w = 0.f;
#pragma unroll 8
    for (int t = 0; t < WCH; t++) w += vp[(size_t)t * DIM] * gs[hh][t];
    g_ws[((b * NWC + c) << 10) + (hq * 8 + hh) * DD + d] = w;
}

// ------------- k_w2: exclusive prefix over chunks ------------------------
__global__ __launch_bounds__(1024) void k_w2() {
    int b = blockIdx.x;                  // 4
    int tid = threadIdx.x;               // 1024 = h*64+d
    float v[NWC];
#pragma unroll
    for (int c = 0; c < NWC; c++) v[c] = g_ws[((b * NWC + c) << 10) + tid];
    float p = 0.f;
#pragma unroll
    for (int c = 0; c < NWC; c++) {
        g_wpre[((b * NWC + c) << 10) + tid] = p;
        p += v[c];
    }
}

// ------------- k_w3: cumsum + h = w*r, fused head-mean (batched) ---------
__global__ __launch_bounds__(1024) void k_w3() {
    int c = blockIdx.x;                  // 32
    int b = blockIdx.y;                  // 4
    int tid = threadIdx.x;               // 1024 = h*64+d
    int h = tid >> 6, d = tid & 63;
    __shared__ float gs[16][64];
    __shared__ float rs[16][64];
    __shared__ float red[4][16][65];     // 4-t batch, padded
    __shared__ float red2[4][4][68];     // partial head sums
    gs[h][d] = g_gq[(size_t)(b * HH + h) * TT + c * WCH + d];
    rs[h][d] = g_rq[(size_t)(b * HH + h) * TT + c * WCH + d];
    float w = g_wpre[((b * NWC + c) << 10) + tid];
    int row0 = b * TT + c * WCH;
    const float* vp = g_v + (size_t)row0 * DIM + tid;
    __syncthreads();

    int k2 = tid >> 8;                   // 0..3 (t within batch)
    int hq = (tid >> 6) & 3;             // 0..3 (head quarter)
    int d2 = tid & 63;

    float vbuf[2][4];
#pragma unroll
    for (int k = 0; k < 4; k++) vbuf[0][k] = vp[(size_t)k * DIM];

    for (int t = 0; t < WCH; t += 4) {
        int cur = (t >> 2) & 1, nxt = cur ^ 1;
        if (t + 4 < WCH) {
#pragma unroll
            for (int k = 0; k < 4; k++) vbuf[nxt][k] = vp[(size_t)(t + 4 + k) * DIM];
        }
#pragma unroll
        for (int k = 0; k < 4; k++) {
            int tt = t + k;
            w += vbuf[cur][k] * gs[h][tt];
            red[k][h][d] = w * rs[h][tt];
        }
        __syncthreads();
        float p = red[k2][hq * 4 + 0][d2] + red[k2][hq * 4 + 1][d2]
                + red[k2][hq * 4 + 2][d2] + red[k2][hq * 4 + 3][d2];
        red2[k2][hq][d2] = p;
        __syncthreads();
        if (tid < 256) {
            int kk = tid >> 6, dd = tid & 63;
            float s = red2[kk][0][dd] + red2[kk][1][dd]
                    + red2[kk][2][dd] + red2[kk][3][dd];
            g_hmean[(size_t)(row0 + t + kk) * DD + dd] = s * 0.0625f;
        }
        __syncthreads();
    }
}

// ---------------- output GEMM: out = hmean @ out_w^T + b -----------------
__global__ void gemm_out(const float* __restrict__ out_w,
                         const float* __restrict__ out_b,
                         float* __restrict__ out) {
    __shared__ float Hs[64][65];
    __shared__ float Ws[64][68];
    int m0 = blockIdx.y * 64, n0 = blockIdx.x * 64;
    int tid = threadIdx.x;
    const float* hsrc = g_hmean + (size_t)m0 * DD;
    for (int i = tid; i < 64 * 64; i += 256) Hs[i >> 6][i & 63] = hsrc[i];
    for (int i = tid; i < 64 * 64; i += 256) {
        int o = i >> 6, d = i & 63;
        Ws[d][o] = out_w[(size_t)(n0 + o) * DD + d];
    }
    __syncthreads();
    int tr = tid >> 4, tc = tid & 15;
    float acc[4][4];
#pragma unroll
    for (int i = 0; i < 4; i++)
#pragma unroll
        for (int j = 0; j < 4; j++) acc[i][j] = 0.f;
#pragma unroll 8
    for (int k = 0; k < 64; k++) {
        float a[4], bv[4];
#pragma unroll
        for (int i = 0; i < 4; i++) a[i] = Hs[tr * 4 + i][k];
#pragma unroll
        for (int j = 0; j < 4; j++) bv[j] = Ws[k][tc * 4 + j];
#pragma unroll
        for (int i = 0; i < 4; i++)
#pragma unroll
            for (int j = 0; j < 4; j++) acc[i][j] += a[i] * bv[j];
    }
    float bo[4];
#pragma unroll
    for (int j = 0; j < 4; j++) bo[j] = out_b[n0 + tc * 4 + j];
#pragma unroll
    for (int i = 0; i < 4; i++) {
        float4 v4 = make_float4(acc[i][0] + bo[0], acc[i][1] + bo[1],
                                acc[i][2] + bo[2], acc[i][3] + bo[3]);
        *(float4*)(out + (size_t)(m0 + tr * 4 + i) * DOUT + n0 + tc * 4) = v4;
    }
}

// ---------------- launch -------------------------------------------------
extern "C" void kernel_launch(void* const* d_in, const int* in_sizes, int n_in,
                              void* d_out, int out_size) {
    const float* x    = (const float*)d_in[0];   // [4,2048,1024]
    const float* kvk  = (const float*)d_in[1];   // [1024,16,64,2]
    const float* q    = (const float*)d_in[2];   // [16,64]
    const float* outw = (const float*)d_in[3];   // [1024,64]
    const float* outb = (const float*)d_in[4];   // [1024]
    float* out = (float*)d_out;                  // [4,2048,1024]

    cudaFuncSetAttribute(gemm_v_tc, cudaFuncAttributeMaxDynamicSharedMemorySize,
                         GV_SMEM_TOTAL);

    pack_x<<<(BT * DIM / 4) / 256, 256>>>(x);
    pack_w<<<dim3(DIM / 32, DIM / 32), 256>>>(kvk);
    pack_qk<<<(DIM * HH + 255) / 256, 256>>>(kvk, q);
    pack_qkT<<<(HH * DIM) / 256, 256>>>();
    gemm_st_tc<<<BT / 64, 128, ST_SMEM_TOTAL>>>();
    k_g<<<NBH, 128>>>();
    gemm_v_tc<<<dim3(DIM / GV_TN, BT / GV_TM), 128, GV_SMEM_TOTAL>>>();
    k_w1<<<dim3(NWC, 2, BB), 512>>>();
    k_w2<<<BB, 1024>>>();
    k_w3<<<dim3(NWC, BB), 1024>>>();
    gemm_out<<<dim3(DOUT / 64, BT / 64), 256>>>(outw, outb, out);
}

// round 14
// speedup vs baseline: 2.1618x; 1.0066x over previous
#include <cuda_runtime.h>
#include <cuda_bf16.h>
#include <math_constants.h>
#include <cstdint>

// Problem constants
#define BB 4
#define TT 2048
#define BT 8192          // B*T
#define DIM 1024
#define HH 16
#define DD 64            // DIM_INNER
#define DOUT 1024
#define WCH 64           // w-pipeline chunk rows
#define NWC (TT / WCH)   // 32
#define NBH (BB * HH)    // 64

// ===================== PTX helpers (non-'a' safe: sm_80+) =================
__device__ __forceinline__ uint32_t smem_u32(const void* p) {
    uint32_t a;
    asm("{ .reg .u64 t; cvta.to.shared.u64 t, %1; cvt.u32.u64 %0, t; }" : "=r"(a) : "l"(p));
    return a;
}
#define CP_ASYNC16(dst, src) \
    asm volatile("cp.async.cg.shared.global [%0], [%1], 16;" :: "r"(dst), "l"(src))
#define CP_COMMIT() asm volatile("cp.async.commit_group;" ::: "memory")
#define CP_WAIT1() asm volatile("cp.async.wait_group 1;" ::: "memory")
#define CP_WAIT0() asm volatile("cp.async.wait_group 0;" ::: "memory")
#define SW128(off) ((off) ^ (((off) >> 3) & 0x70))

#define LDMATRIX_X4(r0, r1, r2, r3, addr)                                     \
    asm volatile("ldmatrix.sync.aligned.m8n8.x4.shared.b16 {%0,%1,%2,%3}, [%4];" \
                 : "=r"(r0), "=r"(r1), "=r"(r2), "=r"(r3) : "r"(addr))

#define MMA_BF16(c0, c1, c2, c3, a0, a1, a2, a3, b0, b1)                      \
    asm volatile("mma.sync.aligned.m16n8k16.row.col.f32.bf16.bf16.f32 "       \
                 "{%0,%1,%2,%3}, {%4,%5,%6,%7}, {%8,%9}, {%0,%1,%2,%3};"      \
                 : "+f"(c0), "+f"(c1), "+f"(c2), "+f"(c3)                     \
                 : "r"(a0), "r"(a1), "r"(a2), "r"(a3), "r"(b0), "r"(b1))

// ---------------- scratch (device globals; no allocations allowed) -------
__device__ __nv_bfloat16 g_xh[(size_t)BT * DIM];      // x hi (bf16)
__device__ __nv_bfloat16 g_xl[(size_t)BT * DIM];      // x lo (bf16)
__device__ __nv_bfloat16 g_wh[(size_t)DIM * DIM];     // Wv^T hi : [n][k]
__device__ __nv_bfloat16 g_wl[(size_t)DIM * DIM];     // Wv^T lo : [n][k]
__device__ __nv_bfloat16 g_qkTh[HH * DIM];            // qk^T hi : [h][k]
__device__ __nv_bfloat16 g_qkTl[HH * DIM];            // qk^T lo : [h][k]
__device__ float g_v[(size_t)BT * DIM];               // v activations
__device__ float g_stT[NBH * TT];                     // scores [bh][t]
__device__ float g_gq[NBH * TT];                      // g_t = exp(st - m*)
__device__ float g_rq[NBH * TT];                      // r_t = 1 / cumsum(g)
__device__ float g_ws[BB * NWC * DIM];                // chunk sums of v*g
__device__ float g_hmean[BT * DD];                    // head-mean

// ---------------- pack_all: x split, Wv transpose+split, qk fold+split ---
// grid: [0,8192) pack_x f4 blocks; [8192,9216) pack_w 32x32 tiles;
//       [9216,9280) qk fold blocks.
__global__ void pack_all(const float* __restrict__ x,
                         const float* __restrict__ kvk,
                         const float* __restrict__ q) {
    int bx = blockIdx.x;
    int tid = threadIdx.x;
    if (bx < 8192) {                     // ---- pack_x ----
        int idx = bx * 256 + tid;        // float4 index over BT*DIM/4
        float4 a = ((const float4*)x)[idx];
        __nv_bfloat16 h0 = __float2bfloat16_rn(a.x), h1 = __float2bfloat16_rn(a.y);
        __nv_bfloat16 h2 = __float2bfloat16_rn(a.z), h3 = __float2bfloat16_rn(a.w);
        __nv_bfloat162* ph = (__nv_bfloat162*)g_xh;
        __nv_bfloat162* pl = (__nv_bfloat162*)g_xl;
        ph[idx * 2 + 0] = __nv_bfloat162(h0, h1);
        ph[idx * 2 + 1] = __nv_bfloat162(h2, h3);
        __nv_bfloat16 l0 = __float2bfloat16_rn(a.x - __bfloat162float(h0));
        __nv_bfloat16 l1 = __float2bfloat16_rn(a.y - __bfloat162float(h1));
        __nv_bfloat16 l2 = __float2bfloat16_rn(a.z - __bfloat162float(h2));
        __nv_bfloat16 l3 = __float2bfloat16_rn(a.w - __bfloat162float(h3));
        pl[idx * 2 + 0] = __nv_bfloat162(l0, l1);
        pl[idx * 2 + 1] = __nv_bfloat162(l2, l3);
    } else if (bx < 9216) {              // ---- pack_w ----
        __shared__ float tile[32][33];
        int q2 = bx - 8192;
        int bi = (q2 & 31) * 32;         // k (i) base
        int bn = (q2 >> 5) * 32;         // n base
        int tx = tid & 31, ty = tid >> 5;   // 32x8
#pragma unroll
        for (int k = 0; k < 4; k++) {
            int il = ty + k * 8;
            tile[il][tx] = kvk[(size_t)(bi + il) * 2048 + (bn + tx) * 2 + 1];
        }
        __syncthreads();
#pragma unroll
        for (int k = 0; k < 4; k++) {
            int nl = ty + k * 8;
            float a = tile[tx][nl];
            __nv_bfloat16 h = __float2bfloat16_rn(a);
            __nv_bfloat16 l = __float2bfloat16_rn(a - __bfloat162float(h));
            g_wh[(size_t)(bn + nl) * DIM + bi + tx] = h;
            g_wl[(size_t)(bn + nl) * DIM + bi + tx] = l;
        }
    } else {                             // ---- qk fold + transposed split ----
        int idx = (bx - 9216) * 256 + tid;   // over 1024*16
        int i = idx >> 4, h = idx & 15;
        const float* kp = kvk + (size_t)i * 2048 + h * 128;  // (h*64+o)*2, k=0
        const float* qp = q + h * DD;
        float s = 0.f;
#pragma unroll
        for (int o = 0; o < DD; o++) s += qp[o] * kp[o * 2];
        __nv_bfloat16 hi = __float2bfloat16_rn(s);
        g_qkTh[h * DIM + i] = hi;
        g_qkTl[h * DIM + i] = __float2bfloat16_rn(s - __bfloat162float(hi));
    }
}

// ====== fused GEMM: v = x @ Wv  AND  st = x @ qk  (split-bf16, mma.sync) ==
// grid (9, 64): bx<8 -> v-tile CTA (n0=bx*128, m0=by*128), 4 warps 2x2,
// warp 64x64, 3-stage cp.async. bx==8 -> st CTA for rows [by*128, +128),
// 4 warps x 32 rows, N=16 from qkT tile in the Q smem region.
#define GV_TM 128
#define GV_TN 128
#define GV_NCHUNK 48
#define GV_A_BYTES (GV_TM * 128)                 // 16 KB
#define GV_B_BYTES (GV_TN * 128)                 // 16 KB
#define GV_Q_BYTES (16 * 128)                    // 2 KB
#define GV_STAGE_BYTES (GV_A_BYTES + GV_B_BYTES + GV_Q_BYTES) // 34816
#define GV_SMEM_TOTAL (3 * GV_STAGE_BYTES)       // 104448

__global__ __launch_bounds__(128, 2) void gemm_vst() {
    extern __shared__ char smem[];
    uint32_t sbase = smem_u32(smem);
    int tid = threadIdx.x;
    int wid = tid >> 5, lane = tid & 31;
    int m0 = blockIdx.y * GV_TM;
    const uint32_t stage_off[3] = {0u, (uint32_t)GV_STAGE_BYTES, (uint32_t)(2 * GV_STAGE_BYTES)};
    int a_row = lane & 15, a_cs = lane >> 4;
    int b_row = ((lane >> 4) << 3) + (lane & 7), b_cs = (lane >> 3) & 1;
    int gid = lane >> 2, tig = lane & 3;

    if (blockIdx.x == 8) {
        // ---------------- st path: 128 rows x 16 heads ----------------
        float acc[2][2][4];
#pragma unroll
        for (int mi = 0; mi < 2; mi++)
#pragma unroll
            for (int ni = 0; ni < 2; ni++)
#pragma unroll
                for (int j = 0; j < 4; j++) acc[mi][ni][j] = 0.f;

        auto load_chunk_st = [&](int c, uint32_t so) {
            int p = c >> 4;
            int kc = (c & 15) << 6;
            const __nv_bfloat16* gA = (p < 2) ? g_xh : g_xl;
            const __nv_bfloat16* gQ = (p == 1) ? g_qkTl : g_qkTh;
#pragma unroll
            for (int i = 0; i < 8; i++) {          // A: 128 rows x 8 segs
                int seg = tid + (i << 7);
                int r = seg >> 3, jb = seg & 7;
                uint32_t off = (uint32_t)((r << 7) + (jb << 4));
                CP_ASYNC16(sbase + so + SW128(off),
                           gA + (size_t)(m0 + r) * DIM + kc + (jb << 3));
            }
            {                                       // Q: 16 rows x 8 segs
                int r = tid >> 3, jb = tid & 7;
                uint32_t off = (uint32_t)((r << 7) + (jb << 4));
                CP_ASYNC16(sbase + so + GV_A_BYTES + GV_B_BYTES + SW128(off),
                           gQ + (size_t)r * DIM + kc + (jb << 3));
            }
            CP_COMMIT();
        };

        load_chunk_st(0, stage_off[0]);
        load_chunk_st(1, stage_off[1]);
        for (int c = 0; c < GV_NCHUNK; c++) {
            int s = c % 3;
            if (c < GV_NCHUNK - 1) CP_WAIT1(); else CP_WAIT0();
            __syncthreads();
            if (c + 2 < GV_NCHUNK) load_chunk_st(c + 2, stage_off[(c + 2) % 3]);
            uint32_t abase = sbase + stage_off[s];
            uint32_t qbase = sbase + stage_off[s] + GV_A_BYTES + GV_B_BYTES;
#pragma unroll
            for (int ks = 0; ks < 4; ks++) {
                uint32_t afr[2][4];
#pragma unroll
                for (int mi = 0; mi < 2; mi++) {
                    int row = wid * 32 + mi * 16 + a_row;
                    uint32_t off = (uint32_t)((row << 7) + ((ks * 2 + a_cs) << 4));
                    LDMATRIX_X4(afr[mi][0], afr[mi][1], afr[mi][2], afr[mi][3],
                                abase + SW128(off));
                }
                uint32_t bq[2][2];
                {
                    uint32_t off = (uint32_t)((b_row << 7) + ((ks * 2 + b_cs) << 4));
                    uint32_t r0, r1, r2, r3;
                    LDMATRIX_X4(r0, r1, r2, r3, qbase + SW128(off));
                    bq[0][0] = r0; bq[0][1] = r1;
                    bq[1][0] = r2; bq[1][1] = r3;
                }
#pragma unroll
                for (int mi = 0; mi < 2; mi++)
#pragma unroll
                    for (int ni = 0; ni < 2; ni++)
                        MMA_BF16(acc[mi][ni][0], acc[mi][ni][1], acc[mi][ni][2], acc[mi][ni][3],
                                 afr[mi][0], afr[mi][1], afr[mi][2], afr[mi][3],
                                 bq[ni][0], bq[ni][1]);
            }
        }
#pragma unroll
        for (int mi = 0; mi < 2; mi++) {
            int r = m0 + wid * 32 + mi * 16 + gid;
            int b = r >> 11;
            int t0 = r & 2047, t8 = (r + 8) & 2047;
#pragma unroll
            for (int ni = 0; ni < 2; ni++) {
                int h0 = ni * 8 + tig * 2;
                g_stT[(size_t)(b * HH + h0) * TT + t0]     = acc[mi][ni][0];
                g_stT[(size_t)(b * HH + h0 + 1) * TT + t0] = acc[mi][ni][1];
                g_stT[(size_t)(b * HH + h0) * TT + t8]     = acc[mi][ni][2];
                g_stT[(size_t)(b * HH + h0 + 1) * TT + t8] = acc[mi][ni][3];
            }
        }
        return;
    }

    // ---------------- v path: CTA tile 128x128 ----------------
    int n0 = blockIdx.x * GV_TN;
    int wm = wid >> 1;
    int wn = wid & 1;

    float acc[4][8][4];
#pragma unroll
    for (int mi = 0; mi < 4; mi++)
#pragma unroll
        for (int ni = 0; ni < 8; ni++)
#pragma unroll
            for (int j = 0; j < 4; j++) acc[mi][ni][j] = 0.f;

    auto load_chunk = [&](int c, uint32_t so) {
        int p = c >> 4;
        int kc = (c & 15) << 6;
        const __nv_bfloat16* gA = (p < 2) ? g_xh : g_xl;
        const __nv_bfloat16* gB = (p == 1) ? g_wl : g_wh;
#pragma unroll
        for (int i = 0; i < 16; i++) {
            int seg = tid + (i << 7);
            if (seg < 1024) {
                int r = seg >> 3, jb = seg & 7;
                uint32_t off = (uint32_t)((r << 7) + (jb << 4));
                CP_ASYNC16(sbase + so + SW128(off),
                           gA + (size_t)(m0 + r) * DIM + kc + (jb << 3));
            } else {
                int s2 = seg - 1024;
                int n = s2 >> 3, jb = s2 & 7;
                uint32_t off = (uint32_t)((n << 7) + (jb << 4));
                CP_ASYNC16(sbase + so + GV_A_BYTES + SW128(off),
                           gB + (size_t)(n0 + n) * DIM + kc + (jb << 3));
            }
        }
        CP_COMMIT();
    };

    load_chunk(0, stage_off[0]);
    load_chunk(1, stage_off[1]);

    for (int c = 0; c < GV_NCHUNK; c++) {
        int s = c % 3;
        if (c < GV_NCHUNK - 1) CP_WAIT1(); else CP_WAIT0();
        __syncthreads();
        if (c + 2 < GV_NCHUNK) load_chunk(c + 2, stage_off[(c + 2) % 3]);

        uint32_t abase = sbase + stage_off[s];
        uint32_t bbase = sbase + stage_off[s] + GV_A_BYTES;
#pragma unroll
        for (int ks = 0; ks < 4; ks++) {
            uint32_t afr[4][4];
#pragma unroll
            for (int mi = 0; mi < 4; mi++) {
                int row = wm * 64 + mi * 16 + a_row;
                uint32_t off = (uint32_t)((row << 7) + ((ks * 2 + a_cs) << 4));
                LDMATRIX_X4(afr[mi][0], afr[mi][1], afr[mi][2], afr[mi][3],
                            abase + SW128(off));
            }
            uint32_t bfr[8][2];
#pragma unroll
            for (int nj = 0; nj < 4; nj++) {
                int row = wn * 64 + nj * 16 + b_row;
                uint32_t off = (uint32_t)((row << 7) + ((ks * 2 + b_cs) << 4));
                uint32_t r0, r1, r2, r3;
                LDMATRIX_X4(r0, r1, r2, r3, bbase + SW128(off));
                bfr[nj * 2 + 0][0] = r0; bfr[nj * 2 + 0][1] = r1;
                bfr[nj * 2 + 1][0] = r2; bfr[nj * 2 + 1][1] = r3;
            }
#pragma unroll
            for (int mi = 0; mi < 4; mi++)
#pragma unroll
                for (int ni = 0; ni < 8; ni++)
                    MMA_BF16(acc[mi][ni][0], acc[mi][ni][1], acc[mi][ni][2], acc[mi][ni][3],
                             afr[mi][0], afr[mi][1], afr[mi][2], afr[mi][3],
                             bfr[ni][0], bfr[ni][1]);
        }
    }

#pragma unroll
    for (int mi = 0; mi < 4; mi++) {
        int r0 = m0 + wm * 64 + mi * 16 + gid;
#pragma unroll
        for (int ni = 0; ni < 8; ni++) {
            int col = n0 + wn * 64 + ni * 8 + tig * 2;
            *(float2*)(g_v + (size_t)r0 * DIM + col) =
                make_float2(acc[mi][ni][0], acc[mi][ni][1]);
            *(float2*)(g_v + (size_t)(r0 + 8) * DIM + col) =
                make_float2(acc[mi][ni][2], acc[mi][ni][3]);
        }
    }
}

// ------------- k_g: per-(bh) max, g_t = exp(st-m*), r_t = 1/cumsum(g) ----
__global__ __launch_bounds__(128) void k_g() {
    int bh = blockIdx.x;                 // 64
    int tid = threadIdx.x;               // 128, each owns 16 consecutive t
    const float* stp = g_stT + (size_t)bh * TT;
    float s[16];
#pragma unroll
    for (int j = 0; j < 16; j++) s[j] = stp[tid * 16 + j];
    float lm = s[0];
#pragma unroll
    for (int j = 1; j < 16; j++) lm = fmaxf(lm, s[j]);
    __shared__ float sc[128];
    sc[tid] = lm;
    __syncthreads();
#pragma unroll
    for (int off = 64; off > 0; off >>= 1) {
        if (tid < off) sc[tid] = fmaxf(sc[tid], sc[tid + off]);
        __syncthreads();
    }
    float mstar = sc[0];
    __syncthreads();
    float g[16];
    float run = 0.f;
#pragma unroll
    for (int j = 0; j < 16; j++) { g[j] = __expf(s[j] - mstar); run += g[j]; }
    sc[tid] = run;
    __syncthreads();
#pragma unroll
    for (int off = 1; off < 128; off <<= 1) {
        float v = (tid >= off) ? sc[tid - off] : 0.f;
        __syncthreads();
        sc[tid] += v;
        __syncthreads();
    }
    float cum = (tid == 0) ? 0.f : sc[tid - 1];   // exclusive, additions-only
    float* gg = g_gq + (size_t)bh * TT + tid * 16;
    float* gr = g_rq + (size_t)bh * TT + tid * 16;
#pragma unroll
    for (int j = 0; j < 16; j++) {
        cum += g[j];
        gg[j] = g[j];
        gr[j] = __fdividef(1.f, fmaxf(cum, 1e-37f));
    }
}

// ------------- k_w1: chunk sums of v*g over 64-row chunks ----------------
__global__ __launch_bounds__(512) void k_w1() {
    int c = blockIdx.x;                  // 32
    int hq = blockIdx.y;                 // 2
    int b = blockIdx.z;                  // 4
    int tid = threadIdx.x;               // 512: hh(8) x d(64)
    int hh = tid >> 6, d = tid & 63;
    __shared__ float gs[8][64];
    gs[hh][d] = g_gq[(size_t)(b * HH + hq * 8 + hh) * TT + c * WCH + d];
    __syncthreads();
    int row0 = b * TT + c * WCH;
    const float* vp = g_v + (size_t)row0 * DIM + (hq * 8 + hh) * DD + d;
    float w = 0.f;
#pragma unroll 8
    for (int t = 0; t < WCH; t++) w += vp[(size_t)t * DIM] * gs[hh][t];
    g_ws[((b * NWC + c) << 10) + (hq * 8 + hh) * DD + d] = w;
}

// ------------- k_w3: chunk prefix + cumsum + h = w*r, fused head-mean ----
__global__ __launch_bounds__(1024) void k_w3() {
    int c = blockIdx.x;                  // 32
    int b = blockIdx.y;                  // 4
    int tid = threadIdx.x;               // 1024 = h*64+d
    int h = tid >> 6, d = tid & 63;
    __shared__ float gs[16][64];
    __shared__ float rs[16][64];
    __shared__ float red[4][16][65];     // 4-t batch, padded
    __shared__ float red2[4][4][68];     // partial head sums
    gs[h][d] = g_gq[(size_t)(b * HH + h) * TT + c * WCH + d];
    rs[h][d] = g_rq[(size_t)(b * HH + h) * TT + c * WCH + d];
    // exclusive chunk prefix computed in-place (same order as old k_w2)
    float w = 0.f;
    for (int cc = 0; cc < c; cc++) w += g_ws[((b * NWC + cc) << 10) + tid];
    int row0 = b * TT + c * WCH;
    const float* vp = g_v + (size_t)row0 * DIM + tid;
    __syncthreads();

    int k2 = tid >> 8;                   // 0..3 (t within batch)
    int hq = (tid >> 6) & 3;             // 0..3 (head quarter)
    int d2 = tid & 63;

    float vbuf[2][4];
#pragma unroll
    for (int k = 0; k < 4; k++) vbuf[0][k] = vp[(size_t)k * DIM];

    for (int t = 0; t < WCH; t += 4) {
        int cur = (t >> 2) & 1, nxt = cur ^ 1;
        if (t + 4 < WCH) {
#pragma unroll
            for (int k = 0; k < 4; k++) vbuf[nxt][k] = vp[(size_t)(t + 4 + k) * DIM];
        }
#pragma unroll
        for (int k = 0; k < 4; k++) {
            int tt = t + k;
            w += vbuf[cur][k] * gs[h][tt];
            red[k][h][d] = w * rs[h][tt];
        }
        __syncthreads();
        float p = red[k2][hq * 4 + 0][d2] + red[k2][hq * 4 + 1][d2]
                + red[k2][hq * 4 + 2][d2] + red[k2][hq * 4 + 3][d2];
        red2[k2][hq][d2] = p;
        __syncthreads();
        if (tid < 256) {
            int kk = tid >> 6, dd = tid & 63;
            float s = red2[kk][0][dd] + red2[kk][1][dd]
                    + red2[kk][2][dd] + red2[kk][3][dd];
            g_hmean[(size_t)(row0 + t + kk) * DD + dd] = s * 0.0625f;
        }
        __syncthreads();
    }
}

// ---------------- output GEMM: out = hmean @ out_w^T + b -----------------
__global__ void gemm_out(const float* __restrict__ out_w,
                         const float* __restrict__ out_b,
                         float* __restrict__ out) {
    __shared__ float Hs[64][65];
    __shared__ float Ws[64][68];
    int m0 = blockIdx.y * 64, n0 = blockIdx.x * 64;
    int tid = threadIdx.x;
    const float* hsrc = g_hmean + (size_t)m0 * DD;
    for (int i = tid; i < 64 * 64; i += 256) Hs[i >> 6][i & 63] = hsrc[i];
    for (int i = tid; i < 64 * 64; i += 256) {
        int o = i >> 6, d = i & 63;
        Ws[d][o] = out_w[(size_t)(n0 + o) * DD + d];
    }
    __syncthreads();
    int tr = tid >> 4, tc = tid & 15;
    float acc[4][4];
#pragma unroll
    for (int i = 0; i < 4; i++)
#pragma unroll
        for (int j = 0; j < 4; j++) acc[i][j] = 0.f;
#pragma unroll 8
    for (int k = 0; k < 64; k++) {
        float a[4], bv[4];
#pragma unroll
        for (int i = 0; i < 4; i++) a[i] = Hs[tr * 4 + i][k];
#pragma unroll
        for (int j = 0; j < 4; j++) bv[j] = Ws[k][tc * 4 + j];
#pragma unroll
        for (int i = 0; i < 4; i++)
#pragma unroll
            for (int j = 0; j < 4; j++) acc[i][j] += a[i] * bv[j];
    }
    float bo[4];
#pragma unroll
    for (int j = 0; j < 4; j++) bo[j] = out_b[n0 + tc * 4 + j];
#pragma unroll
    for (int i = 0; i < 4; i++) {
        float4 v4 = make_float4(acc[i][0] + bo[0], acc[i][1] + bo[1],
                                acc[i][2] + bo[2], acc[i][3] + bo[3]);
        *(float4*)(out + (size_t)(m0 + tr * 4 + i) * DOUT + n0 + tc * 4) = v4;
    }
}

// ---------------- launch -------------------------------------------------
extern "C" void kernel_launch(void* const* d_in, const int* in_sizes, int n_in,
                              void* d_out, int out_size) {
    const float* x    = (const float*)d_in[0];   // [4,2048,1024]
    const float* kvk  = (const float*)d_in[1];   // [1024,16,64,2]
    const float* q    = (const float*)d_in[2];   // [16,64]
    const float* outw = (const float*)d_in[3];   // [1024,64]
    const float* outb = (const float*)d_in[4];   // [1024]
    float* out = (float*)d_out;                  // [4,2048,1024]

    cudaFuncSetAttribute(gemm_vst, cudaFuncAttributeMaxDynamicSharedMemorySize,
                         GV_SMEM_TOTAL);

    pack_all<<<8192 + 1024 + 64, 256>>>(x, kvk, q);
    gemm_vst<<<dim3(9, BT / GV_TM), 128, GV_SMEM_TOTAL>>>();
    k_g<<<NBH, 128>>>();
    k_w1<<<dim3(NWC, 2, BB), 512>>>();
    k_w3<<<dim3(NWC, BB), 1024>>>();
    gemm_out<<<dim3(DOUT / 64, BT / 64), 256>>>(outw, outb, out);
}